// round 14
// baseline (speedup 1.0000x reference)
#include <cuda_runtime.h>
#include <cuda_bf16.h>
#include <mma.h>
#include <cstdint>
#include <stdint.h>
#include <math.h>
#include <string.h>

using namespace nvcuda;

#define BB 2
#define C0 64
#define DWC 128
#define HH 160
#define WW 160
#define HW (HH*WW)
#define NPIX (BB*HW)
#define HP 162
#define WP 162
#define NOUT (BB*C0*HW)

// plain bf16 weight tiles [oc][cin] (element offsets)
#define OFF_PW1  0
#define OFF_VAL  8192
#define OFF_OM   24576
#define OFF_OUTP 40960
#define OFF_C3   57344
#define OFF_C4   65536
#define OFF_C5   81920
#define WBF_TOT  86016

// ---------------- scratch ----------------
__device__ float g_h[(size_t)NPIX*DWC];
__device__ float g_vp[(size_t)BB*HP*WP*DWC];
__device__ float g_dw[(size_t)NPIX*DWC];
__device__ float g_om[(size_t)NPIX*112];
__device__ float g_s[(size_t)NPIX*DWC];
__device__ float g_feat[(size_t)2*NPIX*C0];
__device__ float g_g4[(size_t)NPIX*C0];
__device__ float g_part[400*64];
__device__ float g_scale[BB*DWC];
__device__ float g_ycat[(size_t)NPIX*DWC];
__device__ __nv_bfloat16 g_wbf[WBF_TOT];

extern __shared__ __align__(16) char smc[];

__device__ __forceinline__ uint32_t b2u(__nv_bfloat162 h) { uint32_t u; memcpy(&u, &h, 4); return u; }
__device__ __forceinline__ float4 ldg4(const float* p) { return *(const float4*)p; }

// ---------------- staging helpers ----------------
// B: plain global [N][K] bf16 -> smem [N][K+8]
template<int K>
__device__ __forceinline__ void copy_B_pad(const __nv_bfloat16* gw, __nv_bfloat16* b_sm, int N) {
    const int SEGS = K / 8;   // 16B segments per row
    for (int i = threadIdx.x; i < N * SEGS; i += 256) {
        int row = i / SEGS, seg = i - row * SEGS;
        uint4 v = ((const uint4*)gw)[i];
        *(uint4*)(b_sm + row * (K + 8) + seg * 8) = v;
    }
}
// A: NHWC fp32 (K channels/pixel) -> smem bf16 [128][K+8]; 2 threads per row
template<int K>
__device__ __forceinline__ void stage_A_nhwc(const float* __restrict__ src, __nv_bfloat16* a_sm, int base) {
    int row = threadIdx.x >> 1, half = threadIdx.x & 1;
    const float* s = src + (size_t)(base + row) * K + half * (K / 2);
    __nv_bfloat16* d = a_sm + row * (K + 8) + half * (K / 2);
    #pragma unroll
    for (int k = 0; k < K / 2; k += 8) {
        float4 v0 = *(const float4*)(s + k);
        float4 v1 = *(const float4*)(s + k + 4);
        uint4 o;
        o.x = b2u(__floats2bfloat162_rn(v0.x, v0.y));
        o.y = b2u(__floats2bfloat162_rn(v0.z, v0.w));
        o.z = b2u(__floats2bfloat162_rn(v1.x, v1.y));
        o.w = b2u(__floats2bfloat162_rn(v1.z, v1.w));
        *(uint4*)(d + k) = o;
    }
}

// ---------------- core wmma GEMM: M=128 (8 warps x 16 rows), accum -> OUT smem ----------------
template<int K, int N>
__device__ __forceinline__ void wgemm(const __nv_bfloat16* a_sm, const __nv_bfloat16* b_sm, float* out_f) {
    const int warp = threadIdx.x >> 5;
    const int LDA = K + 8;
    const int LDO = N + 4;
    wmma::fragment<wmma::accumulator, 16, 16, 16, float> acc[N / 16];
    #pragma unroll
    for (int n = 0; n < N / 16; n++) wmma::fill_fragment(acc[n], 0.f);
    #pragma unroll
    for (int k = 0; k < K; k += 16) {
        wmma::fragment<wmma::matrix_a, 16, 16, 16, __nv_bfloat16, wmma::row_major> af;
        wmma::load_matrix_sync(af, a_sm + warp * 16 * LDA + k, LDA);
        #pragma unroll
        for (int n = 0; n < N / 16; n++) {
            wmma::fragment<wmma::matrix_b, 16, 16, 16, __nv_bfloat16, wmma::col_major> bf;
            wmma::load_matrix_sync(bf, b_sm + n * 16 * LDA + k, LDA);
            wmma::mma_sync(acc[n], af, bf, acc[n]);
        }
    }
    float* ow = out_f + warp * 16 * LDO;
    #pragma unroll
    for (int n = 0; n < N / 16; n++)
        wmma::store_matrix_sync(ow + n * 16, acc[n], LDO, wmma::mem_row_major);
}

// ---------------- weight prep ----------------
__global__ __launch_bounds__(256) void k_prep_w(
    const float* __restrict__ pw1_w, const float* __restrict__ val_w,
    const float* __restrict__ om_w, const float* __restrict__ outp_w,
    const float* __restrict__ c3_w, const float* __restrict__ c4_w,
    const float* __restrict__ c5_w)
{
    int m = blockIdx.y;
    int N, K, rows, base;
    const float* src;
    switch (m) {
        case 0: N = 128; K = 64;  rows = 128; base = OFF_PW1;  src = pw1_w;  break;
        case 1: N = 128; K = 128; rows = 128; base = OFF_VAL;  src = val_w;  break;
        case 2: N = 128; K = 128; rows = 112; base = OFF_OM;   src = om_w;   break;
        case 3: N = 128; K = 128; rows = 128; base = OFF_OUTP; src = outp_w; break;
        case 4: N = 64;  K = 128; rows = 64;  base = OFF_C3;   src = c3_w;   break;
        case 5: N = 128; K = 128; rows = 128; base = OFF_C4;   src = c4_w;   break;
        default:N = 64;  K = 64;  rows = 64;  base = OFF_C5;   src = c5_w;   break;
    }
    int idx = blockIdx.x * 256 + threadIdx.x;
    if (idx >= N * K) return;
    int row = idx / K;
    float v = (row < rows) ? src[idx] : 0.f;
    g_wbf[base + idx] = __float2bfloat16(v);
}

// ---------------- LN1 + pw1 (K=64 -> N=128) ----------------
__global__ __launch_bounds__(256) void k_mm_pw1(const float* __restrict__ x,
                                                const float* __restrict__ g,
                                                const float* __restrict__ bias) {
    const int K = 64, N = 128;
    const int A_ELEMS = 128 * (K + 8), B_ELEMS = N * (K + 8);
    __nv_bfloat16* a_sm = (__nv_bfloat16*)smc;
    __nv_bfloat16* b_sm = a_sm + A_ELEMS;
    float* out_f = (float*)(b_sm + B_ELEMS);
    int t = threadIdx.x;
    int base = blockIdx.x * 128;
    // LN1: 2 threads per pixel, 32 channels each (NCHW strided)
    {
        int row = t >> 1, half = t & 1;
        int pix = base + row;
        int b = pix / HW, hw = pix % HW;
        const float* xb = x + (size_t)b * C0 * HW + (size_t)(half * 32) * HW + hw;
        float v[32];
        float s1 = 0.f, s2 = 0.f;
        #pragma unroll
        for (int c = 0; c < 32; c++) { v[c] = xb[(size_t)c * HW]; s1 += v[c]; s2 += v[c] * v[c]; }
        s1 += __shfl_xor_sync(0xffffffffu, s1, 1);
        s2 += __shfl_xor_sync(0xffffffffu, s2, 1);
        float mu = s1 * (1.f / 64.f);
        float var = s2 * (1.f / 64.f) - mu * mu;
        float r = rsqrtf(var + 1e-5f);
        __nv_bfloat16* d = a_sm + row * (K + 8) + half * 32;
        #pragma unroll
        for (int c = 0; c < 32; c += 4) {
            float o0 = (v[c] - mu) * r * __ldg(g + half * 32 + c);
            float o1 = (v[c + 1] - mu) * r * __ldg(g + half * 32 + c + 1);
            float o2 = (v[c + 2] - mu) * r * __ldg(g + half * 32 + c + 2);
            float o3 = (v[c + 3] - mu) * r * __ldg(g + half * 32 + c + 3);
            uint2 p = make_uint2(b2u(__floats2bfloat162_rn(o0, o1)), b2u(__floats2bfloat162_rn(o2, o3)));
            *(uint2*)(d + c) = p;
        }
    }
    copy_B_pad<K>(g_wbf + OFF_PW1, b_sm, N);
    __syncthreads();
    wgemm<K, N>(a_sm, b_sm, out_f);
    int warp = t >> 5, lane = t & 31;
    float* ow = out_f + warp * 16 * 132;
    int c0 = lane * 4;
    float4 bv = ldg4(bias + c0);
    #pragma unroll
    for (int r = 0; r < 16; r++) {
        int pix = base + warp * 16 + r;
        float4 v = *(float4*)(ow + r * 132 + c0);
        v.x += bv.x; v.y += bv.y; v.z += bv.z; v.w += bv.w;
        *(float4*)(g_h + (size_t)pix * DWC + c0) = v;
    }
}

// ---------------- val (K=128 -> N=128, scatter to padded vp) ----------------
__global__ __launch_bounds__(256) void k_mm_val(const float* __restrict__ bias) {
    const int K = 128, N = 128;
    const int A_ELEMS = 128 * (K + 8), B_ELEMS = N * (K + 8);
    __nv_bfloat16* a_sm = (__nv_bfloat16*)smc;
    __nv_bfloat16* b_sm = a_sm + A_ELEMS;
    float* out_f = (float*)(b_sm + B_ELEMS);
    int base = blockIdx.x * 128;
    stage_A_nhwc<K>(g_h, a_sm, base);
    copy_B_pad<K>(g_wbf + OFF_VAL, b_sm, N);
    __syncthreads();
    wgemm<K, N>(a_sm, b_sm, out_f);
    int warp = threadIdx.x >> 5, lane = threadIdx.x & 31;
    float* ow = out_f + warp * 16 * 132;
    int c0 = lane * 4;
    float4 bv = ldg4(bias + c0);
    #pragma unroll
    for (int r = 0; r < 16; r++) {
        int pix = base + warp * 16 + r;
        int b = pix / HW, hw = pix % HW;
        int y = hw / WW, xx = hw % WW;
        float4 v = *(float4*)(ow + r * 132 + c0);
        v.x += bv.x; v.y += bv.y; v.z += bv.z; v.w += bv.w;
        *(float4*)(g_vp + ((size_t)(b * HP + y + 1) * WP + (xx + 1)) * DWC + c0) = v;
    }
}

// ---------------- om (K=128 -> N=112 padded to 128) ----------------
__global__ __launch_bounds__(256) void k_mm_om(const float* __restrict__ bias) {
    const int K = 128, N = 128;
    const int A_ELEMS = 128 * (K + 8), B_ELEMS = N * (K + 8);
    __nv_bfloat16* a_sm = (__nv_bfloat16*)smc;
    __nv_bfloat16* b_sm = a_sm + A_ELEMS;
    float* out_f = (float*)(b_sm + B_ELEMS);
    int base = blockIdx.x * 128;
    stage_A_nhwc<K>(g_dw, a_sm, base);
    copy_B_pad<K>(g_wbf + OFF_OM, b_sm, N);
    __syncthreads();
    wgemm<K, N>(a_sm, b_sm, out_f);
    int warp = threadIdx.x >> 5, lane = threadIdx.x & 31;
    float* ow = out_f + warp * 16 * 132;
    int c0 = lane * 4;
    if (c0 < 112) {
        float4 bv = ldg4(bias + c0);
        #pragma unroll
        for (int r = 0; r < 16; r++) {
            int pix = base + warp * 16 + r;
            float4 v = *(float4*)(ow + r * 132 + c0);
            v.x += bv.x; v.y += bv.y; v.z += bv.z; v.w += bv.w;
            *(float4*)(g_om + (size_t)pix * 112 + c0) = v;
        }
    }
}

// ---------------- outp (K=128 -> N=128) + SimpleGate -> 64 ----------------
__global__ __launch_bounds__(256) void k_mm_outp(const float* __restrict__ bias, int br) {
    const int K = 128, N = 128;
    const int A_ELEMS = 128 * (K + 8), B_ELEMS = N * (K + 8);
    __nv_bfloat16* a_sm = (__nv_bfloat16*)smc;
    __nv_bfloat16* b_sm = a_sm + A_ELEMS;
    float* out_f = (float*)(b_sm + B_ELEMS);
    int base = blockIdx.x * 128;
    stage_A_nhwc<K>(g_s, a_sm, base);
    copy_B_pad<K>(g_wbf + OFF_OUTP, b_sm, N);
    __syncthreads();
    wgemm<K, N>(a_sm, b_sm, out_f);
    int warp = threadIdx.x >> 5, lane = threadIdx.x & 31;
    float* ow = out_f + warp * 16 * 132;
    float* fo = g_feat + (size_t)br * NPIX * C0;
    #pragma unroll
    for (int i = 0; i < 8; i++) {
        int idx = i * 32 + lane;
        int r = idx >> 4, c0 = (idx & 15) * 4;
        int pix = base + warp * 16 + r;
        float4 a = *(float4*)(ow + r * 132 + c0);
        float4 b = *(float4*)(ow + r * 132 + c0 + 64);
        float4 ba = ldg4(bias + c0), bb = ldg4(bias + c0 + 64);
        float4 o;
        o.x = (a.x + ba.x) * (b.x + bb.x);
        o.y = (a.y + ba.y) * (b.y + bb.y);
        o.z = (a.z + ba.z) * (b.z + bb.z);
        o.w = (a.w + ba.w) * (b.w + bb.w);
        *(float4*)(fo + (size_t)pix * C0 + c0) = o;
    }
}

// ---------------- conv3 (K=128 -> N=64) + SE prologue + residual epilogue ----------------
__global__ __launch_bounds__(256) void k_mm_conv3(const float* __restrict__ bias,
                                                  const float* __restrict__ xl,
                                                  const float* __restrict__ xr,
                                                  const float* __restrict__ beta) {
    const int K = 128, N = 64;
    const int A_ELEMS = 128 * (K + 8), B_ELEMS = N * (K + 8);
    __nv_bfloat16* a_sm = (__nv_bfloat16*)smc;
    __nv_bfloat16* b_sm = a_sm + A_ELEMS;
    float* out_f = (float*)(b_sm + B_ELEMS);
    int t = threadIdx.x;
    int base = blockIdx.x * 128;
    // prologue: concat(feat_l, feat_r) * scale; 2 threads per pixel (half = branch)
    {
        int row = t >> 1, half = t & 1;
        int pix = base + row;
        int b = pix / HW;
        const float* f = g_feat + (size_t)half * NPIX * C0 + (size_t)pix * C0;
        const float* sc = g_scale + b * 128 + half * 64;
        __nv_bfloat16* d = a_sm + row * (K + 8) + half * 64;
        #pragma unroll
        for (int c = 0; c < 64; c += 8) {
            float4 v0 = *(const float4*)(f + c);
            float4 v1 = *(const float4*)(f + c + 4);
            uint4 o;
            o.x = b2u(__floats2bfloat162_rn(v0.x * sc[c], v0.y * sc[c + 1]));
            o.y = b2u(__floats2bfloat162_rn(v0.z * sc[c + 2], v0.w * sc[c + 3]));
            o.z = b2u(__floats2bfloat162_rn(v1.x * sc[c + 4], v1.y * sc[c + 5]));
            o.w = b2u(__floats2bfloat162_rn(v1.z * sc[c + 6], v1.w * sc[c + 7]));
            *(uint4*)(d + c) = o;
        }
    }
    copy_B_pad<K>(g_wbf + OFF_C3, b_sm, N);
    __syncthreads();
    wgemm<K, N>(a_sm, b_sm, out_f);
    int warp = t >> 5, lane = t & 31;
    float* ow = out_f + warp * 16 * 68;
    #pragma unroll
    for (int i = 0; i < 8; i++) {
        int idx = i * 32 + lane;
        int r = idx >> 4, c0 = (idx & 15) * 4;
        int pix = base + warp * 16 + r;
        int b = pix / HW, hw = pix % HW;
        float4 v = *(float4*)(ow + r * 68 + c0);
        float4 bv = ldg4(bias + c0), bt = ldg4(beta + c0);
        float x30 = (v.x + bv.x) * bt.x;
        float x31 = (v.y + bv.y) * bt.y;
        float x32 = (v.z + bv.z) * bt.z;
        float x33 = (v.w + bv.w) * bt.w;
        const float* xlb = xl + (size_t)b * C0 * HW + (size_t)c0 * HW + hw;
        const float* xrb = xr + (size_t)b * C0 * HW + (size_t)c0 * HW + hw;
        float4 yl, yr2;
        yl.x = xlb[0] + x30;          yl.y = xlb[(size_t)HW] + x31;
        yl.z = xlb[(size_t)2 * HW] + x32; yl.w = xlb[(size_t)3 * HW] + x33;
        yr2.x = xrb[0] + x30;          yr2.y = xrb[(size_t)HW] + x31;
        yr2.z = xrb[(size_t)2 * HW] + x32; yr2.w = xrb[(size_t)3 * HW] + x33;
        *(float4*)(g_ycat + (size_t)pix * DWC + c0) = yl;
        *(float4*)(g_ycat + (size_t)pix * DWC + 64 + c0) = yr2;
    }
}

// ---------------- LN2 + conv4 (K=128 -> N=128) + SimpleGate -> 64 ----------------
__global__ __launch_bounds__(256) void k_mm_ln2c4(const float* __restrict__ g2,
                                                  const float* __restrict__ bias) {
    const int K = 128, N = 128;
    const int A_ELEMS = 128 * (K + 8), B_ELEMS = N * (K + 8);
    __nv_bfloat16* a_sm = (__nv_bfloat16*)smc;
    __nv_bfloat16* b_sm = a_sm + A_ELEMS;
    float* out_f = (float*)(b_sm + B_ELEMS);
    int t = threadIdx.x;
    int base = blockIdx.x * 128;
    {
        int row = t >> 1, half = t & 1;
        int pix = base + row;
        const float* yr = g_ycat + (size_t)pix * DWC + half * 64;
        float v[64];
        float s1 = 0.f, s2 = 0.f;
        #pragma unroll
        for (int c = 0; c < 64; c += 4) {
            float4 a = *(const float4*)(yr + c);
            v[c] = a.x; v[c + 1] = a.y; v[c + 2] = a.z; v[c + 3] = a.w;
            s1 += a.x + a.y + a.z + a.w;
            s2 += a.x * a.x + a.y * a.y + a.z * a.z + a.w * a.w;
        }
        s1 += __shfl_xor_sync(0xffffffffu, s1, 1);
        s2 += __shfl_xor_sync(0xffffffffu, s2, 1);
        float mu = s1 * (1.f / 128.f);
        float var = s2 * (1.f / 128.f) - mu * mu;
        float rs = rsqrtf(var + 1e-5f);
        __nv_bfloat16* d = a_sm + row * (K + 8) + half * 64;
        #pragma unroll
        for (int c = 0; c < 64; c += 4) {
            float o0 = (v[c] - mu) * rs * __ldg(g2 + half * 64 + c);
            float o1 = (v[c + 1] - mu) * rs * __ldg(g2 + half * 64 + c + 1);
            float o2 = (v[c + 2] - mu) * rs * __ldg(g2 + half * 64 + c + 2);
            float o3 = (v[c + 3] - mu) * rs * __ldg(g2 + half * 64 + c + 3);
            uint2 p = make_uint2(b2u(__floats2bfloat162_rn(o0, o1)), b2u(__floats2bfloat162_rn(o2, o3)));
            *(uint2*)(d + c) = p;
        }
    }
    copy_B_pad<K>(g_wbf + OFF_C4, b_sm, N);
    __syncthreads();
    wgemm<K, N>(a_sm, b_sm, out_f);
    int warp = t >> 5, lane = t & 31;
    float* ow = out_f + warp * 16 * 132;
    #pragma unroll
    for (int i = 0; i < 8; i++) {
        int idx = i * 32 + lane;
        int r = idx >> 4, c0 = (idx & 15) * 4;
        int pix = base + warp * 16 + r;
        float4 a = *(float4*)(ow + r * 132 + c0);
        float4 b = *(float4*)(ow + r * 132 + c0 + 64);
        float4 ba = ldg4(bias + c0), bb = ldg4(bias + c0 + 64);
        float4 o;
        o.x = (a.x + ba.x) * (b.x + bb.x);
        o.y = (a.y + ba.y) * (b.y + bb.y);
        o.z = (a.z + ba.z) * (b.z + bb.z);
        o.w = (a.w + ba.w) * (b.w + bb.w);
        *(float4*)(g_g4 + (size_t)pix * C0 + c0) = o;
    }
}

// ---------------- conv5 (K=64 -> N=64) + final residuals -> NCHW out ----------------
__global__ __launch_bounds__(256) void k_mm_conv5(const float* __restrict__ bias,
                                                  const float* __restrict__ gamma,
                                                  float* __restrict__ out) {
    const int K = 64, N = 64;
    const int A_ELEMS = 128 * (K + 8), B_ELEMS = N * (K + 8);
    __nv_bfloat16* a_sm = (__nv_bfloat16*)smc;
    __nv_bfloat16* b_sm = a_sm + A_ELEMS;
    float* out_f = (float*)(b_sm + B_ELEMS);
    int base = blockIdx.x * 128;
    stage_A_nhwc<K>(g_g4, a_sm, base);
    copy_B_pad<K>(g_wbf + OFF_C5, b_sm, N);
    __syncthreads();
    wgemm<K, N>(a_sm, b_sm, out_f);
    int warp = threadIdx.x >> 5, lane = threadIdx.x & 31;
    float* ow = out_f + warp * 16 * 68;
    #pragma unroll
    for (int i = 0; i < 8; i++) {
        int idx = i * 32 + lane;
        int r = idx >> 4, c0 = (idx & 15) * 4;
        int pix = base + warp * 16 + r;
        int b = pix / HW, hw = pix % HW;
        float4 v = *(float4*)(ow + r * 68 + c0);
        float4 bv = ldg4(bias + c0), gm = ldg4(gamma + c0);
        float z0 = (v.x + bv.x) * gm.x;
        float z1 = (v.y + bv.y) * gm.y;
        float z2 = (v.z + bv.z) * gm.z;
        float z3 = (v.w + bv.w) * gm.w;
        const float* yr = g_ycat + (size_t)pix * DWC;
        float* o0 = out + (size_t)b * C0 * HW + (size_t)c0 * HW + hw;
        o0[0] = yr[c0] + z0;
        o0[(size_t)HW] = yr[c0 + 1] + z1;
        o0[(size_t)2 * HW] = yr[c0 + 2] + z2;
        o0[(size_t)3 * HW] = yr[c0 + 3] + z3;
        float* o1 = o0 + (size_t)NOUT;
        o1[0] = yr[64 + c0] + z0;
        o1[(size_t)HW] = yr[64 + c0 + 1] + z1;
        o1[(size_t)2 * HW] = yr[64 + c0 + 2] + z2;
        o1[(size_t)3 * HW] = yr[64 + c0 + 3] + z3;
    }
}

// ---------------- non-GEMM kernels (unchanged from passing r7) ----------------
__global__ void k_zero_vp() {
    size_t i = (size_t)blockIdx.x * 256 + threadIdx.x;
    size_t n4 = (size_t)BB * HP * WP * DWC / 4;
    if (i < n4) reinterpret_cast<float4*>(g_vp)[i] = make_float4(0.f, 0.f, 0.f, 0.f);
}

__global__ __launch_bounds__(256) void k_dwc(const float* __restrict__ w,
                                             const float* __restrict__ bias) {
    int tid = blockIdx.x * 256 + threadIdx.x;
    if (tid >= NPIX * 32) return;
    int c4 = (tid & 31) * 4;
    int pix = tid >> 5;
    int b = pix / HW, hw = pix % HW;
    int y = hw / WW, x = hw % WW;
    float4 acc = *reinterpret_cast<const float4*>(bias + c4);
    #pragma unroll
    for (int ky = 0; ky < 3; ky++) {
        int yy = y + ky - 1;
        if (yy < 0 || yy >= HH) continue;
        #pragma unroll
        for (int kx = 0; kx < 3; kx++) {
            int xx = x + kx - 1;
            if (xx < 0 || xx >= WW) continue;
            float4 v = *reinterpret_cast<const float4*>(
                g_h + ((size_t)b * HW + (size_t)yy * WW + xx) * DWC + c4);
            float4 wv = *reinterpret_cast<const float4*>(w + (ky * 3 + kx) * DWC + c4);
            acc.x = fmaf(v.x, wv.x, acc.x);
            acc.y = fmaf(v.y, wv.y, acc.y);
            acc.z = fmaf(v.z, wv.z, acc.z);
            acc.w = fmaf(v.w, wv.w, acc.w);
        }
    }
    *reinterpret_cast<float4*>(g_dw + (size_t)pix * DWC + c4) = acc;
}

__global__ __launch_bounds__(256) void k_sample() {
    __shared__ float som[224];
    int t = threadIdx.x;
    int base = blockIdx.x * 2;
    for (int i = t; i < 224; i += 256) som[i] = g_om[(size_t)base * 112 + i];
    __syncthreads();
    int wp = t >> 5, lane = t & 31;
    int pi = wp >> 2, g = wp & 3;
    int pix = base + pi;
    int b = pix / HW, hw = pix % HW;
    int y = hw / WW, x = hw % WW;
    const float* om = som + pi * 112 + g * 27;
    int gc = g * 32 + lane;
    const float* vpb = g_vp + (size_t)b * HP * WP * DWC + gc;
    float acc = 0.f;
    #pragma unroll
    for (int k = 0; k < 9; k++) {
        float offx = om[k * 3 + 0];
        float offy = om[k * 3 + 1];
        float mask = om[k * 3 + 2];
        float px = (float)(x + (k % 3)) + offx;
        float py = (float)(y + (k / 3)) + offy;
        float x0f = floorf(px), y0f = floorf(py);
        float tx = px - x0f, ty = py - y0f;
        int x0 = (int)x0f, y0 = (int)y0f;
        #pragma unroll
        for (int dy = 0; dy < 2; dy++) {
            #pragma unroll
            for (int dx = 0; dx < 2; dx++) {
                int xi = x0 + dx, yi = y0 + dy;
                float wg = (dx ? tx : 1.f - tx) * (dy ? ty : 1.f - ty);
                bool valid = (xi >= 0) & (xi < WP) & (yi >= 0) & (yi < HP);
                wg = valid ? wg * mask : 0.f;
                int xc = min(max(xi, 0), WP - 1);
                int yc = min(max(yi, 0), HP - 1);
                acc = fmaf(wg, vpb[((size_t)yc * WP + xc) * DWC], acc);
            }
        }
    }
    g_s[(size_t)pix * DWC + gc] = acc;
}

__global__ __launch_bounds__(256) void k_pool1() {
    __shared__ float red[256];
    int blk = blockIdx.x;
    int chunk = blk % 100;
    int bb = (blk / 100) & 1;
    int br = blk / 200;
    int pix0 = bb * HW + chunk * 256;
    int c = threadIdx.x & 63, sub = threadIdx.x >> 6;
    const float* f = g_feat + (size_t)br * NPIX * C0 + (size_t)(pix0 + sub * 64) * C0 + c;
    float s = 0.f;
    #pragma unroll 4
    for (int p = 0; p < 64; p++) s += f[(size_t)p * C0];
    red[threadIdx.x] = s;
    __syncthreads();
    if (sub == 0)
        g_part[blk * 64 + c] = red[c] + red[64 + c] + red[128 + c] + red[192 + c];
}

__global__ __launch_bounds__(256) void k_pool_scale(const float* __restrict__ sw,
                                                    const float* __restrict__ sb) {
    __shared__ float pooled[2 * 128];
    int t = threadIdx.x;
    int b = t >> 7, cc = t & 127;
    int br = cc >> 6, c = cc & 63;
    float s = 0.f;
    for (int ch = 0; ch < 100; ch++)
        s += g_part[((br * 2 + b) * 100 + ch) * 64 + c];
    pooled[b * 128 + cc] = s * (1.f / (float)HW);
    __syncthreads();
    float acc = sb[cc];
    #pragma unroll 4
    for (int k = 0; k < 128; k++) acc = fmaf(sw[cc * 128 + k], pooled[b * 128 + k], acc);
    g_scale[b * 128 + cc] = acc;
}

// ---------------- host launch ----------------
extern "C" void kernel_launch(void* const* d_in, const int* in_sizes, int n_in,
                              void* d_out, int out_size) {
    const float* x_l     = (const float*)d_in[0];
    const float* x_r     = (const float*)d_in[1];
    const float* ln1_g   = (const float*)d_in[2];
    const float* pw1_w   = (const float*)d_in[3];
    const float* pw1_b   = (const float*)d_in[4];
    const float* val_w   = (const float*)d_in[5];
    const float* val_b   = (const float*)d_in[6];
    const float* dwc_w   = (const float*)d_in[7];
    const float* dwc_b   = (const float*)d_in[8];
    const float* om_w    = (const float*)d_in[9];
    const float* om_b    = (const float*)d_in[10];
    const float* outp_w  = (const float*)d_in[11];
    const float* outp_b  = (const float*)d_in[12];
    const float* sca_w   = (const float*)d_in[13];
    const float* sca_b   = (const float*)d_in[14];
    const float* conv3_w = (const float*)d_in[15];
    const float* conv3_b = (const float*)d_in[16];
    const float* norm2_g = (const float*)d_in[17];
    const float* conv4_w = (const float*)d_in[18];
    const float* conv4_b = (const float*)d_in[19];
    const float* conv5_w = (const float*)d_in[20];
    const float* conv5_b = (const float*)d_in[21];
    const float* beta    = (const float*)d_in[22];
    const float* gamma   = (const float*)d_in[23];
    float* out = (float*)d_out;

    // smem sizes: A + B (bf16, LDA=K+8) + OUT (fp32, LDO=N+4)
    const int SM_PW1   = 128*72*2 + 128*72*2 + 128*132*4;   // 104448
    const int SM_VAL   = 128*136*2 + 128*136*2 + 128*132*4; // 137216
    const int SM_OM    = SM_VAL;
    const int SM_OUTP  = SM_VAL;
    const int SM_C3    = 128*136*2 + 64*136*2 + 128*68*4;   // 87040
    const int SM_C4    = SM_VAL;
    const int SM_C5    = 128*72*2 + 64*72*2 + 128*68*4;     // 62464

    cudaFuncSetAttribute(k_mm_pw1,   cudaFuncAttributeMaxDynamicSharedMemorySize, SM_PW1);
    cudaFuncSetAttribute(k_mm_val,   cudaFuncAttributeMaxDynamicSharedMemorySize, SM_VAL);
    cudaFuncSetAttribute(k_mm_om,    cudaFuncAttributeMaxDynamicSharedMemorySize, SM_OM);
    cudaFuncSetAttribute(k_mm_outp,  cudaFuncAttributeMaxDynamicSharedMemorySize, SM_OUTP);
    cudaFuncSetAttribute(k_mm_conv3, cudaFuncAttributeMaxDynamicSharedMemorySize, SM_C3);
    cudaFuncSetAttribute(k_mm_ln2c4, cudaFuncAttributeMaxDynamicSharedMemorySize, SM_C4);
    cudaFuncSetAttribute(k_mm_conv5, cudaFuncAttributeMaxDynamicSharedMemorySize, SM_C5);

    const int NBM = NPIX / 128;  // 400

    k_prep_w<<<dim3(64, 7), 256>>>(pw1_w, val_w, om_w, outp_w, conv3_w, conv4_w, conv5_w);
    k_zero_vp<<<6561, 256>>>();

    for (int br = 0; br < 2; br++) {
        const float* x = br ? x_r : x_l;
        k_mm_pw1<<<NBM, 256, SM_PW1>>>(x, ln1_g, pw1_b);
        k_mm_val<<<NBM, 256, SM_VAL>>>(val_b);
        k_dwc<<<NPIX * 32 / 256, 256>>>(dwc_w, dwc_b);
        k_mm_om<<<NBM, 256, SM_OM>>>(om_b);
        k_sample<<<NPIX / 2, 256>>>();
        k_mm_outp<<<NBM, 256, SM_OUTP>>>(outp_b, br);
    }

    k_pool1<<<400, 256>>>();
    k_pool_scale<<<1, 256>>>(sca_w, sca_b);
    k_mm_conv3<<<NBM, 256, SM_C3>>>(conv3_b, x_l, x_r, beta);
    k_mm_ln2c4<<<NBM, 256, SM_C4>>>(norm2_g, conv4_b);
    k_mm_conv5<<<NBM, 256, SM_C5>>>(conv5_b, gamma, out);
}

// round 15
// speedup vs baseline: 1.4852x; 1.4852x over previous
#include <cuda_runtime.h>
#include <cuda_bf16.h>
#include <mma.h>
#include <cstdint>
#include <stdint.h>
#include <math.h>
#include <string.h>

using namespace nvcuda;

#define BB 2
#define C0 64
#define DWC 128
#define HH 160
#define WW 160
#define HW (HH*WW)
#define NPIX (BB*HW)
#define HP 162
#define WP 162
#define NOUT (BB*C0*HW)

// plain bf16 weight tiles [oc][cin] (element offsets)
#define OFF_PW1  0
#define OFF_VAL  8192
#define OFF_OM   24576
#define OFF_OUTP 40960
#define OFF_C3   57344
#define OFF_C4   65536
#define OFF_C5   81920
#define WBF_TOT  86016

// ---------------- scratch ----------------
__device__ float g_h[(size_t)NPIX*DWC];
__device__ __nv_bfloat16 g_vp[(size_t)BB*HP*WP*DWC];   // padded values, bf16
__device__ float g_dw[(size_t)NPIX*DWC];
__device__ float g_om[(size_t)NPIX*112];
__device__ float g_s[(size_t)NPIX*DWC];
__device__ float g_feat[(size_t)2*NPIX*C0];
__device__ float g_g4[(size_t)NPIX*C0];
__device__ float g_part[400*64];
__device__ float g_scale[BB*DWC];
__device__ float g_ycat[(size_t)NPIX*DWC];
__device__ __nv_bfloat16 g_wbf[WBF_TOT];

extern __shared__ __align__(16) char smc[];

__device__ __forceinline__ uint32_t b2u(__nv_bfloat162 h) { uint32_t u; memcpy(&u, &h, 4); return u; }
__device__ __forceinline__ float4 ldg4(const float* p) { return *(const float4*)p; }

// ---------------- staging helpers (128-thread CTA, M=64 rows) ----------------
// B: plain global [N][K] bf16 -> smem [N][K+8]
template<int K>
__device__ __forceinline__ void copy_B_pad(const __nv_bfloat16* gw, __nv_bfloat16* b_sm, int N) {
    const int SEGS = K / 8;
    for (int i = threadIdx.x; i < N * SEGS; i += 128) {
        int row = i / SEGS, seg = i - row * SEGS;
        uint4 v = ((const uint4*)gw)[i];
        *(uint4*)(b_sm + row * (K + 8) + seg * 8) = v;
    }
}
// A: NHWC fp32 (K channels/pixel) -> smem bf16 [64][K+8]; 2 threads per row
template<int K>
__device__ __forceinline__ void stage_A_nhwc(const float* __restrict__ src, __nv_bfloat16* a_sm, int base) {
    int row = threadIdx.x >> 1, half = threadIdx.x & 1;
    const float* s = src + (size_t)(base + row) * K + half * (K / 2);
    __nv_bfloat16* d = a_sm + row * (K + 8) + half * (K / 2);
    #pragma unroll
    for (int k = 0; k < K / 2; k += 8) {
        float4 v0 = *(const float4*)(s + k);
        float4 v1 = *(const float4*)(s + k + 4);
        uint4 o;
        o.x = b2u(__floats2bfloat162_rn(v0.x, v0.y));
        o.y = b2u(__floats2bfloat162_rn(v0.z, v0.w));
        o.z = b2u(__floats2bfloat162_rn(v1.x, v1.y));
        o.w = b2u(__floats2bfloat162_rn(v1.z, v1.w));
        *(uint4*)(d + k) = o;
    }
}

// ---------------- core wmma GEMM: M=64 (4 warps x 16 rows) ----------------
// After the mainloop, a __syncthreads() and the accumulators are stored into
// out_f, which ALIASES the A/B staging region (smem reuse -> higher occupancy).
template<int K, int N>
__device__ __forceinline__ void wgemm(const __nv_bfloat16* a_sm, const __nv_bfloat16* b_sm, float* out_f) {
    const int warp = threadIdx.x >> 5;
    const int LDA = K + 8;
    const int LDO = N + 4;
    wmma::fragment<wmma::accumulator, 16, 16, 16, float> acc[N / 16];
    #pragma unroll
    for (int n = 0; n < N / 16; n++) wmma::fill_fragment(acc[n], 0.f);
    #pragma unroll
    for (int k = 0; k < K; k += 16) {
        wmma::fragment<wmma::matrix_a, 16, 16, 16, __nv_bfloat16, wmma::row_major> af;
        wmma::load_matrix_sync(af, a_sm + warp * 16 * LDA + k, LDA);
        #pragma unroll
        for (int n = 0; n < N / 16; n++) {
            wmma::fragment<wmma::matrix_b, 16, 16, 16, __nv_bfloat16, wmma::col_major> bf;
            wmma::load_matrix_sync(bf, b_sm + n * 16 * LDA + k, LDA);
            wmma::mma_sync(acc[n], af, bf, acc[n]);
        }
    }
    __syncthreads();   // everyone done reading A/B before overwrite
    float* ow = out_f + warp * 16 * LDO;
    #pragma unroll
    for (int n = 0; n < N / 16; n++)
        wmma::store_matrix_sync(ow + n * 16, acc[n], LDO, wmma::mem_row_major);
    // epilogues read only the warp's own stripe -> no further sync needed
}

// ---------------- weight prep ----------------
__global__ __launch_bounds__(256) void k_prep_w(
    const float* __restrict__ pw1_w, const float* __restrict__ val_w,
    const float* __restrict__ om_w, const float* __restrict__ outp_w,
    const float* __restrict__ c3_w, const float* __restrict__ c4_w,
    const float* __restrict__ c5_w)
{
    int m = blockIdx.y;
    int N, K, rows, base;
    const float* src;
    switch (m) {
        case 0: N = 128; K = 64;  rows = 128; base = OFF_PW1;  src = pw1_w;  break;
        case 1: N = 128; K = 128; rows = 128; base = OFF_VAL;  src = val_w;  break;
        case 2: N = 128; K = 128; rows = 112; base = OFF_OM;   src = om_w;   break;
        case 3: N = 128; K = 128; rows = 128; base = OFF_OUTP; src = outp_w; break;
        case 4: N = 64;  K = 128; rows = 64;  base = OFF_C3;   src = c3_w;   break;
        case 5: N = 128; K = 128; rows = 128; base = OFF_C4;   src = c4_w;   break;
        default:N = 64;  K = 64;  rows = 64;  base = OFF_C5;   src = c5_w;   break;
    }
    int idx = blockIdx.x * 256 + threadIdx.x;
    if (idx >= N * K) return;
    int row = idx / K;
    float v = (row < rows) ? src[idx] : 0.f;
    g_wbf[base + idx] = __float2bfloat16(v);
}

// ---------------- LN1 + pw1 (K=64 -> N=128) ----------------
__global__ __launch_bounds__(128) void k_mm_pw1(const float* __restrict__ x,
                                                const float* __restrict__ g,
                                                const float* __restrict__ bias) {
    const int K = 64, N = 128;
    __nv_bfloat16* a_sm = (__nv_bfloat16*)smc;
    __nv_bfloat16* b_sm = a_sm + 64 * (K + 8);
    float* out_f = (float*)smc;
    int t = threadIdx.x;
    int base = blockIdx.x * 64;
    {
        int row = t >> 1, half = t & 1;
        int pix = base + row;
        int b = pix / HW, hw = pix % HW;
        const float* xb = x + (size_t)b * C0 * HW + (size_t)(half * 32) * HW + hw;
        float v[32];
        float s1 = 0.f, s2 = 0.f;
        #pragma unroll
        for (int c = 0; c < 32; c++) { v[c] = xb[(size_t)c * HW]; s1 += v[c]; s2 += v[c] * v[c]; }
        s1 += __shfl_xor_sync(0xffffffffu, s1, 1);
        s2 += __shfl_xor_sync(0xffffffffu, s2, 1);
        float mu = s1 * (1.f / 64.f);
        float var = s2 * (1.f / 64.f) - mu * mu;
        float r = rsqrtf(var + 1e-5f);
        __nv_bfloat16* d = a_sm + row * (K + 8) + half * 32;
        #pragma unroll
        for (int c = 0; c < 32; c += 4) {
            float o0 = (v[c] - mu) * r * __ldg(g + half * 32 + c);
            float o1 = (v[c + 1] - mu) * r * __ldg(g + half * 32 + c + 1);
            float o2 = (v[c + 2] - mu) * r * __ldg(g + half * 32 + c + 2);
            float o3 = (v[c + 3] - mu) * r * __ldg(g + half * 32 + c + 3);
            uint2 p = make_uint2(b2u(__floats2bfloat162_rn(o0, o1)), b2u(__floats2bfloat162_rn(o2, o3)));
            *(uint2*)(d + c) = p;
        }
    }
    copy_B_pad<K>(g_wbf + OFF_PW1, b_sm, N);
    __syncthreads();
    wgemm<K, N>(a_sm, b_sm, out_f);
    int warp = t >> 5, lane = t & 31;
    float* ow = out_f + warp * 16 * 132;
    int c0 = lane * 4;
    float4 bv = ldg4(bias + c0);
    #pragma unroll
    for (int r = 0; r < 16; r++) {
        int pix = base + warp * 16 + r;
        float4 v = *(float4*)(ow + r * 132 + c0);
        v.x += bv.x; v.y += bv.y; v.z += bv.z; v.w += bv.w;
        *(float4*)(g_h + (size_t)pix * DWC + c0) = v;
    }
}

// ---------------- val (K=128 -> N=128, scatter bf16 into padded vp) ----------------
__global__ __launch_bounds__(128) void k_mm_val(const float* __restrict__ bias) {
    const int K = 128, N = 128;
    __nv_bfloat16* a_sm = (__nv_bfloat16*)smc;
    __nv_bfloat16* b_sm = a_sm + 64 * (K + 8);
    float* out_f = (float*)smc;
    int base = blockIdx.x * 64;
    stage_A_nhwc<K>(g_h, a_sm, base);
    copy_B_pad<K>(g_wbf + OFF_VAL, b_sm, N);
    __syncthreads();
    wgemm<K, N>(a_sm, b_sm, out_f);
    int warp = threadIdx.x >> 5, lane = threadIdx.x & 31;
    float* ow = out_f + warp * 16 * 132;
    int c0 = lane * 4;
    float4 bv = ldg4(bias + c0);
    #pragma unroll
    for (int r = 0; r < 16; r++) {
        int pix = base + warp * 16 + r;
        int b = pix / HW, hw = pix % HW;
        int y = hw / WW, xx = hw % WW;
        float4 v = *(float4*)(ow + r * 132 + c0);
        v.x += bv.x; v.y += bv.y; v.z += bv.z; v.w += bv.w;
        uint2 p = make_uint2(b2u(__floats2bfloat162_rn(v.x, v.y)), b2u(__floats2bfloat162_rn(v.z, v.w)));
        *(uint2*)(g_vp + ((size_t)(b * HP + y + 1) * WP + (xx + 1)) * DWC + c0) = p;
    }
}

// ---------------- om (K=128 -> N=112 padded to 128) ----------------
__global__ __launch_bounds__(128) void k_mm_om(const float* __restrict__ bias) {
    const int K = 128, N = 128;
    __nv_bfloat16* a_sm = (__nv_bfloat16*)smc;
    __nv_bfloat16* b_sm = a_sm + 64 * (K + 8);
    float* out_f = (float*)smc;
    int base = blockIdx.x * 64;
    stage_A_nhwc<K>(g_dw, a_sm, base);
    copy_B_pad<K>(g_wbf + OFF_OM, b_sm, N);
    __syncthreads();
    wgemm<K, N>(a_sm, b_sm, out_f);
    int warp = threadIdx.x >> 5, lane = threadIdx.x & 31;
    float* ow = out_f + warp * 16 * 132;
    int c0 = lane * 4;
    if (c0 < 112) {
        float4 bv = ldg4(bias + c0);
        #pragma unroll
        for (int r = 0; r < 16; r++) {
            int pix = base + warp * 16 + r;
            float4 v = *(float4*)(ow + r * 132 + c0);
            v.x += bv.x; v.y += bv.y; v.z += bv.z; v.w += bv.w;
            *(float4*)(g_om + (size_t)pix * 112 + c0) = v;
        }
    }
}

// ---------------- outp (K=128 -> N=128) + SimpleGate -> 64 ----------------
__global__ __launch_bounds__(128) void k_mm_outp(const float* __restrict__ bias, int br) {
    const int K = 128, N = 128;
    __nv_bfloat16* a_sm = (__nv_bfloat16*)smc;
    __nv_bfloat16* b_sm = a_sm + 64 * (K + 8);
    float* out_f = (float*)smc;
    int base = blockIdx.x * 64;
    stage_A_nhwc<K>(g_s, a_sm, base);
    copy_B_pad<K>(g_wbf + OFF_OUTP, b_sm, N);
    __syncthreads();
    wgemm<K, N>(a_sm, b_sm, out_f);
    int warp = threadIdx.x >> 5, lane = threadIdx.x & 31;
    float* ow = out_f + warp * 16 * 132;
    float* fo = g_feat + (size_t)br * NPIX * C0;
    #pragma unroll
    for (int i = 0; i < 8; i++) {
        int idx = i * 32 + lane;
        int r = idx >> 4, c0 = (idx & 15) * 4;
        int pix = base + warp * 16 + r;
        float4 a = *(float4*)(ow + r * 132 + c0);
        float4 b = *(float4*)(ow + r * 132 + c0 + 64);
        float4 ba = ldg4(bias + c0), bb = ldg4(bias + c0 + 64);
        float4 o;
        o.x = (a.x + ba.x) * (b.x + bb.x);
        o.y = (a.y + ba.y) * (b.y + bb.y);
        o.z = (a.z + ba.z) * (b.z + bb.z);
        o.w = (a.w + ba.w) * (b.w + bb.w);
        *(float4*)(fo + (size_t)pix * C0 + c0) = o;
    }
}

// ---------------- conv3 (K=128 -> N=64) + SE prologue + residual epilogue ----------------
__global__ __launch_bounds__(128) void k_mm_conv3(const float* __restrict__ bias,
                                                  const float* __restrict__ xl,
                                                  const float* __restrict__ xr,
                                                  const float* __restrict__ beta) {
    const int K = 128, N = 64;
    __nv_bfloat16* a_sm = (__nv_bfloat16*)smc;
    __nv_bfloat16* b_sm = a_sm + 64 * (K + 8);
    float* out_f = (float*)smc;
    int t = threadIdx.x;
    int base = blockIdx.x * 64;
    {
        int row = t >> 1, half = t & 1;
        int pix = base + row;
        int b = pix / HW;
        const float* f = g_feat + (size_t)half * NPIX * C0 + (size_t)pix * C0;
        const float* sc = g_scale + b * 128 + half * 64;
        __nv_bfloat16* d = a_sm + row * (K + 8) + half * 64;
        #pragma unroll
        for (int c = 0; c < 64; c += 8) {
            float4 v0 = *(const float4*)(f + c);
            float4 v1 = *(const float4*)(f + c + 4);
            uint4 o;
            o.x = b2u(__floats2bfloat162_rn(v0.x * sc[c], v0.y * sc[c + 1]));
            o.y = b2u(__floats2bfloat162_rn(v0.z * sc[c + 2], v0.w * sc[c + 3]));
            o.z = b2u(__floats2bfloat162_rn(v1.x * sc[c + 4], v1.y * sc[c + 5]));
            o.w = b2u(__floats2bfloat162_rn(v1.z * sc[c + 6], v1.w * sc[c + 7]));
            *(uint4*)(d + c) = o;
        }
    }
    copy_B_pad<K>(g_wbf + OFF_C3, b_sm, N);
    __syncthreads();
    wgemm<K, N>(a_sm, b_sm, out_f);
    int warp = t >> 5, lane = t & 31;
    float* ow = out_f + warp * 16 * 68;
    #pragma unroll
    for (int i = 0; i < 8; i++) {
        int idx = i * 32 + lane;
        int r = idx >> 4, c0 = (idx & 15) * 4;
        int pix = base + warp * 16 + r;
        int b = pix / HW, hw = pix % HW;
        float4 v = *(float4*)(ow + r * 68 + c0);
        float4 bv = ldg4(bias + c0), bt = ldg4(beta + c0);
        float x30 = (v.x + bv.x) * bt.x;
        float x31 = (v.y + bv.y) * bt.y;
        float x32 = (v.z + bv.z) * bt.z;
        float x33 = (v.w + bv.w) * bt.w;
        const float* xlb = xl + (size_t)b * C0 * HW + (size_t)c0 * HW + hw;
        const float* xrb = xr + (size_t)b * C0 * HW + (size_t)c0 * HW + hw;
        float4 yl, yr2;
        yl.x = xlb[0] + x30;              yl.y = xlb[(size_t)HW] + x31;
        yl.z = xlb[(size_t)2 * HW] + x32; yl.w = xlb[(size_t)3 * HW] + x33;
        yr2.x = xrb[0] + x30;              yr2.y = xrb[(size_t)HW] + x31;
        yr2.z = xrb[(size_t)2 * HW] + x32; yr2.w = xrb[(size_t)3 * HW] + x33;
        *(float4*)(g_ycat + (size_t)pix * DWC + c0) = yl;
        *(float4*)(g_ycat + (size_t)pix * DWC + 64 + c0) = yr2;
    }
}

// ---------------- LN2 + conv4 (K=128 -> N=128) + SimpleGate -> 64 ----------------
__global__ __launch_bounds__(128) void k_mm_ln2c4(const float* __restrict__ g2,
                                                  const float* __restrict__ bias) {
    const int K = 128, N = 128;
    __nv_bfloat16* a_sm = (__nv_bfloat16*)smc;
    __nv_bfloat16* b_sm = a_sm + 64 * (K + 8);
    float* out_f = (float*)smc;
    int t = threadIdx.x;
    int base = blockIdx.x * 64;
    {
        int row = t >> 1, half = t & 1;
        int pix = base + row;
        const float* yr = g_ycat + (size_t)pix * DWC + half * 64;
        float v[64];
        float s1 = 0.f, s2 = 0.f;
        #pragma unroll
        for (int c = 0; c < 64; c += 4) {
            float4 a = *(const float4*)(yr + c);
            v[c] = a.x; v[c + 1] = a.y; v[c + 2] = a.z; v[c + 3] = a.w;
            s1 += a.x + a.y + a.z + a.w;
            s2 += a.x * a.x + a.y * a.y + a.z * a.z + a.w * a.w;
        }
        s1 += __shfl_xor_sync(0xffffffffu, s1, 1);
        s2 += __shfl_xor_sync(0xffffffffu, s2, 1);
        float mu = s1 * (1.f / 128.f);
        float var = s2 * (1.f / 128.f) - mu * mu;
        float rs = rsqrtf(var + 1e-5f);
        __nv_bfloat16* d = a_sm + row * (K + 8) + half * 64;
        #pragma unroll
        for (int c = 0; c < 64; c += 4) {
            float o0 = (v[c] - mu) * rs * __ldg(g2 + half * 64 + c);
            float o1 = (v[c + 1] - mu) * rs * __ldg(g2 + half * 64 + c + 1);
            float o2 = (v[c + 2] - mu) * rs * __ldg(g2 + half * 64 + c + 2);
            float o3 = (v[c + 3] - mu) * rs * __ldg(g2 + half * 64 + c + 3);
            uint2 p = make_uint2(b2u(__floats2bfloat162_rn(o0, o1)), b2u(__floats2bfloat162_rn(o2, o3)));
            *(uint2*)(d + c) = p;
        }
    }
    copy_B_pad<K>(g_wbf + OFF_C4, b_sm, N);
    __syncthreads();
    wgemm<K, N>(a_sm, b_sm, out_f);
    int warp = t >> 5, lane = t & 31;
    float* ow = out_f + warp * 16 * 132;
    #pragma unroll
    for (int i = 0; i < 8; i++) {
        int idx = i * 32 + lane;
        int r = idx >> 4, c0 = (idx & 15) * 4;
        int pix = base + warp * 16 + r;
        float4 a = *(float4*)(ow + r * 132 + c0);
        float4 b = *(float4*)(ow + r * 132 + c0 + 64);
        float4 ba = ldg4(bias + c0), bb = ldg4(bias + c0 + 64);
        float4 o;
        o.x = (a.x + ba.x) * (b.x + bb.x);
        o.y = (a.y + ba.y) * (b.y + bb.y);
        o.z = (a.z + ba.z) * (b.z + bb.z);
        o.w = (a.w + ba.w) * (b.w + bb.w);
        *(float4*)(g_g4 + (size_t)pix * C0 + c0) = o;
    }
}

// ---------------- conv5 (K=64 -> N=64) + final residuals -> NCHW out ----------------
__global__ __launch_bounds__(128) void k_mm_conv5(const float* __restrict__ bias,
                                                  const float* __restrict__ gamma,
                                                  float* __restrict__ out) {
    const int K = 64, N = 64;
    __nv_bfloat16* a_sm = (__nv_bfloat16*)smc;
    __nv_bfloat16* b_sm = a_sm + 64 * (K + 8);
    float* out_f = (float*)smc;
    int base = blockIdx.x * 64;
    stage_A_nhwc<K>(g_g4, a_sm, base);
    copy_B_pad<K>(g_wbf + OFF_C5, b_sm, N);
    __syncthreads();
    wgemm<K, N>(a_sm, b_sm, out_f);
    int warp = threadIdx.x >> 5, lane = threadIdx.x & 31;
    float* ow = out_f + warp * 16 * 68;
    #pragma unroll
    for (int i = 0; i < 8; i++) {
        int idx = i * 32 + lane;
        int r = idx >> 4, c0 = (idx & 15) * 4;
        int pix = base + warp * 16 + r;
        int b = pix / HW, hw = pix % HW;
        float4 v = *(float4*)(ow + r * 68 + c0);
        float4 bv = ldg4(bias + c0), gm = ldg4(gamma + c0);
        float z0 = (v.x + bv.x) * gm.x;
        float z1 = (v.y + bv.y) * gm.y;
        float z2 = (v.z + bv.z) * gm.z;
        float z3 = (v.w + bv.w) * gm.w;
        const float* yr = g_ycat + (size_t)pix * DWC;
        float* o0 = out + (size_t)b * C0 * HW + (size_t)c0 * HW + hw;
        o0[0] = yr[c0] + z0;
        o0[(size_t)HW] = yr[c0 + 1] + z1;
        o0[(size_t)2 * HW] = yr[c0 + 2] + z2;
        o0[(size_t)3 * HW] = yr[c0 + 3] + z3;
        float* o1 = o0 + (size_t)NOUT;
        o1[0] = yr[64 + c0] + z0;
        o1[(size_t)HW] = yr[64 + c0 + 1] + z1;
        o1[(size_t)2 * HW] = yr[64 + c0 + 2] + z2;
        o1[(size_t)3 * HW] = yr[64 + c0 + 3] + z3;
    }
}

// ---------------- non-GEMM kernels ----------------
__global__ void k_zero_vp() {
    size_t i = (size_t)blockIdx.x * 256 + threadIdx.x;
    size_t n16 = (size_t)BB * HP * WP * DWC * 2 / 16;
    if (i < n16) reinterpret_cast<uint4*>(g_vp)[i] = make_uint4(0u, 0u, 0u, 0u);
}

__global__ __launch_bounds__(256) void k_dwc(const float* __restrict__ w,
                                             const float* __restrict__ bias) {
    int tid = blockIdx.x * 256 + threadIdx.x;
    if (tid >= NPIX * 32) return;
    int c4 = (tid & 31) * 4;
    int pix = tid >> 5;
    int b = pix / HW, hw = pix % HW;
    int y = hw / WW, x = hw % WW;
    float4 acc = *reinterpret_cast<const float4*>(bias + c4);
    #pragma unroll
    for (int ky = 0; ky < 3; ky++) {
        int yy = y + ky - 1;
        if (yy < 0 || yy >= HH) continue;
        #pragma unroll
        for (int kx = 0; kx < 3; kx++) {
            int xx = x + kx - 1;
            if (xx < 0 || xx >= WW) continue;
            float4 v = *reinterpret_cast<const float4*>(
                g_h + ((size_t)b * HW + (size_t)yy * WW + xx) * DWC + c4);
            float4 wv = *reinterpret_cast<const float4*>(w + (ky * 3 + kx) * DWC + c4);
            acc.x = fmaf(v.x, wv.x, acc.x);
            acc.y = fmaf(v.y, wv.y, acc.y);
            acc.z = fmaf(v.z, wv.z, acc.z);
            acc.w = fmaf(v.w, wv.w, acc.w);
        }
    }
    *reinterpret_cast<float4*>(g_dw + (size_t)pix * DWC + c4) = acc;
}

__global__ __launch_bounds__(256) void k_sample() {
    __shared__ float som[224];
    int t = threadIdx.x;
    int base = blockIdx.x * 2;
    for (int i = t; i < 224; i += 256) som[i] = g_om[(size_t)base * 112 + i];
    __syncthreads();
    int wp = t >> 5, lane = t & 31;
    int pi = wp >> 2, g = wp & 3;
    int pix = base + pi;
    int b = pix / HW, hw = pix % HW;
    int y = hw / WW, x = hw % WW;
    const float* om = som + pi * 112 + g * 27;
    int gc = g * 32 + lane;
    const __nv_bfloat16* vpb = g_vp + (size_t)b * HP * WP * DWC + gc;
    float acc = 0.f;
    #pragma unroll
    for (int k = 0; k < 9; k++) {
        float offx = om[k * 3 + 0];
        float offy = om[k * 3 + 1];
        float mask = om[k * 3 + 2];
        float px = (float)(x + (k % 3)) + offx;
        float py = (float)(y + (k / 3)) + offy;
        float x0f = floorf(px), y0f = floorf(py);
        float tx = px - x0f, ty = py - y0f;
        int x0 = (int)x0f, y0 = (int)y0f;
        #pragma unroll
        for (int dy = 0; dy < 2; dy++) {
            #pragma unroll
            for (int dx = 0; dx < 2; dx++) {
                int xi = x0 + dx, yi = y0 + dy;
                float wg = (dx ? tx : 1.f - tx) * (dy ? ty : 1.f - ty);
                bool valid = (xi >= 0) & (xi < WP) & (yi >= 0) & (yi < HP);
                wg = valid ? wg * mask : 0.f;
                int xc = min(max(xi, 0), WP - 1);
                int yc = min(max(yi, 0), HP - 1);
                acc = fmaf(wg, __bfloat162float(vpb[((size_t)yc * WP + xc) * DWC]), acc);
            }
        }
    }
    g_s[(size_t)pix * DWC + gc] = acc;
}

__global__ __launch_bounds__(256) void k_pool1() {
    __shared__ float red[256];
    int blk = blockIdx.x;
    int chunk = blk % 100;
    int bb = (blk / 100) & 1;
    int br = blk / 200;
    int pix0 = bb * HW + chunk * 256;
    int c = threadIdx.x & 63, sub = threadIdx.x >> 6;
    const float* f = g_feat + (size_t)br * NPIX * C0 + (size_t)(pix0 + sub * 64) * C0 + c;
    float s = 0.f;
    #pragma unroll 4
    for (int p = 0; p < 64; p++) s += f[(size_t)p * C0];
    red[threadIdx.x] = s;
    __syncthreads();
    if (sub == 0)
        g_part[blk * 64 + c] = red[c] + red[64 + c] + red[128 + c] + red[192 + c];
}

__global__ __launch_bounds__(256) void k_pool_scale(const float* __restrict__ sw,
                                                    const float* __restrict__ sb) {
    __shared__ float pooled[2 * 128];
    int t = threadIdx.x;
    int b = t >> 7, cc = t & 127;
    int br = cc >> 6, c = cc & 63;
    float s = 0.f;
    for (int ch = 0; ch < 100; ch++)
        s += g_part[((br * 2 + b) * 100 + ch) * 64 + c];
    pooled[b * 128 + cc] = s * (1.f / (float)HW);
    __syncthreads();
    float acc = sb[cc];
    #pragma unroll 4
    for (int k = 0; k < 128; k++) acc = fmaf(sw[cc * 128 + k], pooled[b * 128 + k], acc);
    g_scale[b * 128 + cc] = acc;
}

// ---------------- host launch ----------------
extern "C" void kernel_launch(void* const* d_in, const int* in_sizes, int n_in,
                              void* d_out, int out_size) {
    const float* x_l     = (const float*)d_in[0];
    const float* x_r     = (const float*)d_in[1];
    const float* ln1_g   = (const float*)d_in[2];
    const float* pw1_w   = (const float*)d_in[3];
    const float* pw1_b   = (const float*)d_in[4];
    const float* val_w   = (const float*)d_in[5];
    const float* val_b   = (const float*)d_in[6];
    const float* dwc_w   = (const float*)d_in[7];
    const float* dwc_b   = (const float*)d_in[8];
    const float* om_w    = (const float*)d_in[9];
    const float* om_b    = (const float*)d_in[10];
    const float* outp_w  = (const float*)d_in[11];
    const float* outp_b  = (const float*)d_in[12];
    const float* sca_w   = (const float*)d_in[13];
    const float* sca_b   = (const float*)d_in[14];
    const float* conv3_w = (const float*)d_in[15];
    const float* conv3_b = (const float*)d_in[16];
    const float* norm2_g = (const float*)d_in[17];
    const float* conv4_w = (const float*)d_in[18];
    const float* conv4_b = (const float*)d_in[19];
    const float* conv5_w = (const float*)d_in[20];
    const float* conv5_b = (const float*)d_in[21];
    const float* beta    = (const float*)d_in[22];
    const float* gamma   = (const float*)d_in[23];
    float* out = (float*)d_out;

    // smem = max(A + B staging, fp32 OUT) — the regions alias
    const int SM_PW1   = 64*132*4;                    // 33792 (> 9216+18432)
    const int SM_VAL   = 64*136*2 + 128*136*2;        // 52224 (> 33792)
    const int SM_OM    = SM_VAL;
    const int SM_OUTP  = SM_VAL;
    const int SM_C4    = SM_VAL;
    const int SM_C3    = 64*136*2 + 64*136*2;         // 34816 (> 17408)
    const int SM_C5    = 64*68*4;                     // 17408 (= OUT; A+B=18432) -> use 18432
    const int SM_C5v   = 64*72*2 + 64*72*2;           // 18432

    cudaFuncSetAttribute(k_mm_pw1,   cudaFuncAttributeMaxDynamicSharedMemorySize, SM_PW1);
    cudaFuncSetAttribute(k_mm_val,   cudaFuncAttributeMaxDynamicSharedMemorySize, SM_VAL);
    cudaFuncSetAttribute(k_mm_om,    cudaFuncAttributeMaxDynamicSharedMemorySize, SM_OM);
    cudaFuncSetAttribute(k_mm_outp,  cudaFuncAttributeMaxDynamicSharedMemorySize, SM_OUTP);
    cudaFuncSetAttribute(k_mm_conv3, cudaFuncAttributeMaxDynamicSharedMemorySize, SM_C3);
    cudaFuncSetAttribute(k_mm_ln2c4, cudaFuncAttributeMaxDynamicSharedMemorySize, SM_C4);
    cudaFuncSetAttribute(k_mm_conv5, cudaFuncAttributeMaxDynamicSharedMemorySize, SM_C5v);

    const int NBM = NPIX / 64;  // 800

    k_prep_w<<<dim3(64, 7), 256>>>(pw1_w, val_w, om_w, outp_w, conv3_w, conv4_w, conv5_w);
    k_zero_vp<<<3281, 256>>>();

    for (int br = 0; br < 2; br++) {
        const float* x = br ? x_r : x_l;
        k_mm_pw1<<<NBM, 128, SM_PW1>>>(x, ln1_g, pw1_b);
        k_mm_val<<<NBM, 128, SM_VAL>>>(val_b);
        k_dwc<<<NPIX * 32 / 256, 256>>>(dwc_w, dwc_b);
        k_mm_om<<<NBM, 128, SM_OM>>>(om_b);
        k_sample<<<NPIX / 2, 256>>>();
        k_mm_outp<<<NBM, 128, SM_OUTP>>>(outp_b, br);
    }

    k_pool1<<<400, 256>>>();
    k_pool_scale<<<1, 256>>>(sca_w, sca_b);
    k_mm_conv3<<<NBM, 128, SM_C3>>>(conv3_b, x_l, x_r, beta);
    k_mm_ln2c4<<<NBM, 128, SM_C4>>>(norm2_g, conv4_b);
    k_mm_conv5<<<NBM, 128, SM_C5v>>>(conv5_b, gamma, out);
}

// round 16
// speedup vs baseline: 1.6196x; 1.0905x over previous
#include <cuda_runtime.h>
#include <cuda_bf16.h>
#include <mma.h>
#include <cstdint>
#include <stdint.h>
#include <math.h>
#include <string.h>

using namespace nvcuda;

#define BB 2
#define C0 64
#define DWC 128
#define HH 160
#define WW 160
#define HW (HH*WW)
#define NPIX (BB*HW)
#define HP 162
#define WP 162
#define NOUT (BB*C0*HW)

// plain bf16 weight tiles [oc][cin] (element offsets)
#define OFF_PW1  0
#define OFF_VAL  8192
#define OFF_OM   24576
#define OFF_OUTP 40960
#define OFF_C3   57344
#define OFF_C4   65536
#define OFF_C5   81920
#define OFF_DWC  86016
#define WBF_TOT  87168

// ---------------- scratch ----------------
__device__ __nv_bfloat16 g_h[(size_t)NPIX*DWC];
__device__ __nv_bfloat16 g_vp[(size_t)BB*HP*WP*DWC];
__device__ __nv_bfloat16 g_dw[(size_t)NPIX*DWC];
__device__ float g_om[(size_t)NPIX*112];
__device__ __nv_bfloat16 g_s[(size_t)NPIX*DWC];
__device__ float g_feat[(size_t)2*NPIX*C0];
__device__ float g_g4[(size_t)NPIX*C0];
__device__ float g_part[400*64];
__device__ float g_scale[BB*DWC];
__device__ float g_ycat[(size_t)NPIX*DWC];
__device__ __nv_bfloat16 g_wbf[WBF_TOT];

extern __shared__ __align__(16) char smc[];

__device__ __forceinline__ uint32_t b2u(__nv_bfloat162 h) { uint32_t u; memcpy(&u, &h, 4); return u; }
__device__ __forceinline__ float4 ldg4(const float* p) { return *(const float4*)p; }

// ---------------- staging helpers (128-thread CTA) ----------------
template<int K>
__device__ __forceinline__ void copy_B_pad(const __nv_bfloat16* gw, __nv_bfloat16* b_sm, int N) {
    const int SEGS = K / 8;
    for (int i = threadIdx.x; i < N * SEGS; i += 128) {
        int row = i / SEGS, seg = i - row * SEGS;
        uint4 v = ((const uint4*)gw)[i];
        *(uint4*)(b_sm + row * (K + 8) + seg * 8) = v;
    }
}
// A: NHWC fp32 -> smem bf16 [64][K+8]
template<int K>
__device__ __forceinline__ void stage_A_nhwc(const float* __restrict__ src, __nv_bfloat16* a_sm, int base) {
    int row = threadIdx.x >> 1, half = threadIdx.x & 1;
    const float* s = src + (size_t)(base + row) * K + half * (K / 2);
    __nv_bfloat16* d = a_sm + row * (K + 8) + half * (K / 2);
    #pragma unroll
    for (int k = 0; k < K / 2; k += 8) {
        float4 v0 = *(const float4*)(s + k);
        float4 v1 = *(const float4*)(s + k + 4);
        uint4 o;
        o.x = b2u(__floats2bfloat162_rn(v0.x, v0.y));
        o.y = b2u(__floats2bfloat162_rn(v0.z, v0.w));
        o.z = b2u(__floats2bfloat162_rn(v1.x, v1.y));
        o.w = b2u(__floats2bfloat162_rn(v1.z, v1.w));
        *(uint4*)(d + k) = o;
    }
}
// A: NHWC bf16 -> smem pure copy [64][K+8]
template<int K>
__device__ __forceinline__ void stage_A_bf16(const __nv_bfloat16* __restrict__ src, __nv_bfloat16* a_sm, int base) {
    int row = threadIdx.x >> 1, half = threadIdx.x & 1;
    const uint4* s = (const uint4*)(src + (size_t)(base + row) * K + half * (K / 2));
    uint4* d = (uint4*)(a_sm + row * (K + 8) + half * (K / 2));
    #pragma unroll
    for (int k = 0; k < K / 16; k++) d[k] = s[k];
}

// ---------------- full-N wgemm (M=64, 4 warps), out aliases smc start ----------------
template<int K, int N>
__device__ __forceinline__ void wgemm(const __nv_bfloat16* a_sm, const __nv_bfloat16* b_sm, float* out_f) {
    const int warp = threadIdx.x >> 5;
    const int LDA = K + 8, LDO = N + 4;
    wmma::fragment<wmma::accumulator, 16, 16, 16, float> acc[N / 16];
    #pragma unroll
    for (int n = 0; n < N / 16; n++) wmma::fill_fragment(acc[n], 0.f);
    #pragma unroll
    for (int k = 0; k < K; k += 16) {
        wmma::fragment<wmma::matrix_a, 16, 16, 16, __nv_bfloat16, wmma::row_major> af;
        wmma::load_matrix_sync(af, a_sm + warp * 16 * LDA + k, LDA);
        #pragma unroll
        for (int n = 0; n < N / 16; n++) {
            wmma::fragment<wmma::matrix_b, 16, 16, 16, __nv_bfloat16, wmma::col_major> bf;
            wmma::load_matrix_sync(bf, b_sm + n * 16 * LDA + k, LDA);
            wmma::mma_sync(acc[n], af, bf, acc[n]);
        }
    }
    __syncthreads();
    float* ow = out_f + warp * 16 * LDO;
    #pragma unroll
    for (int n = 0; n < N / 16; n++)
        wmma::store_matrix_sync(ow + n * 16, acc[n], LDO, wmma::mem_row_major);
}

// ---------------- half-N wgemm (N=64 pass), out aliases the B region ----------------
template<int K>
__device__ __forceinline__ void wgemm64(const __nv_bfloat16* a_sm, const __nv_bfloat16* b_sm, float* out_f) {
    const int warp = threadIdx.x >> 5;
    const int LDA = K + 8, LDO = 68;
    wmma::fragment<wmma::accumulator, 16, 16, 16, float> acc[4];
    #pragma unroll
    for (int n = 0; n < 4; n++) wmma::fill_fragment(acc[n], 0.f);
    #pragma unroll
    for (int k = 0; k < K; k += 16) {
        wmma::fragment<wmma::matrix_a, 16, 16, 16, __nv_bfloat16, wmma::row_major> af;
        wmma::load_matrix_sync(af, a_sm + warp * 16 * LDA + k, LDA);
        #pragma unroll
        for (int n = 0; n < 4; n++) {
            wmma::fragment<wmma::matrix_b, 16, 16, 16, __nv_bfloat16, wmma::col_major> bf;
            wmma::load_matrix_sync(bf, b_sm + n * 16 * LDA + k, LDA);
            wmma::mma_sync(acc[n], af, bf, acc[n]);
        }
    }
    __syncthreads();   // all mma reads of B done before overwrite with out
    float* ow = out_f + warp * 16 * LDO;
    #pragma unroll
    for (int n = 0; n < 4; n++)
        wmma::store_matrix_sync(ow + n * 16, acc[n], LDO, wmma::mem_row_major);
}

// ---------------- weight prep ----------------
__global__ __launch_bounds__(256) void k_prep_w(
    const float* __restrict__ pw1_w, const float* __restrict__ val_w,
    const float* __restrict__ om_w, const float* __restrict__ outp_w,
    const float* __restrict__ c3_w, const float* __restrict__ c4_w,
    const float* __restrict__ c5_w, const float* __restrict__ dwc_w)
{
    int m = blockIdx.y;
    int N, K, rows, base;
    const float* src;
    switch (m) {
        case 0: N = 128; K = 64;  rows = 128; base = OFF_PW1;  src = pw1_w;  break;
        case 1: N = 128; K = 128; rows = 128; base = OFF_VAL;  src = val_w;  break;
        case 2: N = 128; K = 128; rows = 112; base = OFF_OM;   src = om_w;   break;
        case 3: N = 128; K = 128; rows = 128; base = OFF_OUTP; src = outp_w; break;
        case 4: N = 64;  K = 128; rows = 64;  base = OFF_C3;   src = c3_w;   break;
        case 5: N = 128; K = 128; rows = 128; base = OFF_C4;   src = c4_w;   break;
        case 6: N = 64;  K = 64;  rows = 64;  base = OFF_C5;   src = c5_w;   break;
        default:N = 9;   K = 128; rows = 9;   base = OFF_DWC;  src = dwc_w;  break;
    }
    int idx = blockIdx.x * 256 + threadIdx.x;
    if (idx >= N * K) return;
    int row = idx / K;
    float v = (row < rows) ? src[idx] : 0.f;
    g_wbf[base + idx] = __float2bfloat16(v);
}

// ---------------- LN1 + pw1 (K=64 -> N=128), coalesced x load, col-major A ----------------
__global__ __launch_bounds__(128) void k_mm_pw1(const float* __restrict__ x,
                                                const float* __restrict__ g,
                                                const float* __restrict__ bias) {
    const int K = 64, N = 128;
    const int LDA = 72;          // a_sm is [c=64][pix 64 + pad 8] (col-major A for wmma)
    __nv_bfloat16* a_sm = (__nv_bfloat16*)smc;               // 64*72*2 = 9216
    __nv_bfloat16* b_sm = a_sm + 64 * LDA;                   // 128*72*2 = 18432
    float* out_f = (float*)smc;                              // [64][132] f = 33792 (alias)
    int t = threadIdx.x;
    int base = blockIdx.x * 64;
    int b = base / HW, hw0 = base % HW;
    // coalesced stage: x NCHW -> a_sm[c][pix]
    const float* xb = x + (size_t)b * C0 * HW + hw0;
    #pragma unroll
    for (int i = 0; i < 8; i++) {
        int idx = i * 128 + t;
        int c = idx >> 4, pq = idx & 15;
        float4 v = *(const float4*)(xb + (size_t)c * HW + pq * 4);
        uint2 p = make_uint2(b2u(__floats2bfloat162_rn(v.x, v.y)), b2u(__floats2bfloat162_rn(v.z, v.w)));
        *(uint2*)(a_sm + c * LDA + pq * 4) = p;
    }
    copy_B_pad<K>(g_wbf + OFF_PW1, b_sm, N);
    __syncthreads();
    // LN in smem: 2 threads per pixel (adjacent lanes), 32 channels each
    {
        int pix = t >> 1, half = t & 1;
        float vv[32];
        float s1 = 0.f, s2 = 0.f;
        #pragma unroll
        for (int i = 0; i < 32; i++) {
            float v = __bfloat162float(a_sm[(half * 32 + i) * LDA + pix]);
            vv[i] = v; s1 += v; s2 += v * v;
        }
        s1 += __shfl_xor_sync(0xffffffffu, s1, 1);
        s2 += __shfl_xor_sync(0xffffffffu, s2, 1);
        float mu = s1 * (1.f / 64.f);
        float var = s2 * (1.f / 64.f) - mu * mu;
        float r = rsqrtf(var + 1e-5f);
        #pragma unroll
        for (int i = 0; i < 32; i++)
            a_sm[(half * 32 + i) * LDA + pix] = __float2bfloat16((vv[i] - mu) * r * __ldg(g + half * 32 + i));
    }
    __syncthreads();
    // GEMM: A col-major (m=pix contiguous, k=c strided by LDA)
    {
        const int warp = t >> 5;
        wmma::fragment<wmma::accumulator, 16, 16, 16, float> acc[8];
        #pragma unroll
        for (int n = 0; n < 8; n++) wmma::fill_fragment(acc[n], 0.f);
        #pragma unroll
        for (int k = 0; k < K; k += 16) {
            wmma::fragment<wmma::matrix_a, 16, 16, 16, __nv_bfloat16, wmma::col_major> af;
            wmma::load_matrix_sync(af, a_sm + k * LDA + warp * 16, LDA);
            #pragma unroll
            for (int n = 0; n < 8; n++) {
                wmma::fragment<wmma::matrix_b, 16, 16, 16, __nv_bfloat16, wmma::col_major> bf;
                wmma::load_matrix_sync(bf, b_sm + n * 16 * LDA + k, LDA);
                wmma::mma_sync(acc[n], af, bf, acc[n]);
            }
        }
        __syncthreads();
        float* ow = out_f + warp * 16 * 132;
        #pragma unroll
        for (int n = 0; n < 8; n++)
            wmma::store_matrix_sync(ow + n * 16, acc[n], 132, wmma::mem_row_major);
    }
    int warp = t >> 5, lane = t & 31;
    float* ow = out_f + warp * 16 * 132;
    int c0 = lane * 4;
    float4 bv = ldg4(bias + c0);
    #pragma unroll
    for (int r = 0; r < 16; r++) {
        int pix = base + warp * 16 + r;
        float4 v = *(float4*)(ow + r * 132 + c0);
        v.x += bv.x; v.y += bv.y; v.z += bv.z; v.w += bv.w;
        uint2 p = make_uint2(b2u(__floats2bfloat162_rn(v.x, v.y)), b2u(__floats2bfloat162_rn(v.z, v.w)));
        *(uint2*)(g_h + (size_t)pix * DWC + c0) = p;
    }
}

// ---------------- val (K=128 -> N=128, two N=64 passes, 34.8KB smem) ----------------
__global__ __launch_bounds__(128) void k_mm_val(const float* __restrict__ bias) {
    const int K = 128;
    __nv_bfloat16* a_sm = (__nv_bfloat16*)smc;                 // 64*136*2 = 17408
    __nv_bfloat16* b_sm = (__nv_bfloat16*)(smc + 17408);       // 64*136*2 = 17408
    float* out_f = (float*)(smc + 17408);                      // [64][68] f = 17408 (alias B)
    int base = blockIdx.x * 64;
    int warp = threadIdx.x >> 5, lane = threadIdx.x & 31;
    stage_A_bf16<K>(g_h, a_sm, base);
    #pragma unroll
    for (int p = 0; p < 2; p++) {
        copy_B_pad<K>(g_wbf + OFF_VAL + p * 64 * K, b_sm, 64);
        __syncthreads();
        wgemm64<K>(a_sm, b_sm, out_f);
        float* ow = out_f + warp * 16 * 68;
        #pragma unroll
        for (int i = 0; i < 8; i++) {
            int idx = i * 32 + lane;
            int r = idx >> 4, c0 = (idx & 15) * 4;
            int pix = base + warp * 16 + r;
            int b = pix / HW, hw = pix % HW;
            int y = hw / WW, xx = hw % WW;
            float4 v = *(float4*)(ow + r * 68 + c0);
            float4 bv = ldg4(bias + p * 64 + c0);
            v.x += bv.x; v.y += bv.y; v.z += bv.z; v.w += bv.w;
            uint2 o = make_uint2(b2u(__floats2bfloat162_rn(v.x, v.y)), b2u(__floats2bfloat162_rn(v.z, v.w)));
            *(uint2*)(g_vp + ((size_t)(b * HP + y + 1) * WP + (xx + 1)) * DWC + p * 64 + c0) = o;
        }
        __syncthreads();
    }
}

// ---------------- om (K=128 -> N=112, two passes) ----------------
__global__ __launch_bounds__(128) void k_mm_om(const float* __restrict__ bias) {
    const int K = 128;
    __nv_bfloat16* a_sm = (__nv_bfloat16*)smc;
    __nv_bfloat16* b_sm = (__nv_bfloat16*)(smc + 17408);
    float* out_f = (float*)(smc + 17408);
    int base = blockIdx.x * 64;
    int warp = threadIdx.x >> 5, lane = threadIdx.x & 31;
    stage_A_bf16<K>(g_dw, a_sm, base);
    #pragma unroll
    for (int p = 0; p < 2; p++) {
        copy_B_pad<K>(g_wbf + OFF_OM + p * 64 * K, b_sm, 64);
        __syncthreads();
        wgemm64<K>(a_sm, b_sm, out_f);
        float* ow = out_f + warp * 16 * 68;
        int climit = p ? 12 : 16;
        #pragma unroll
        for (int i = 0; i < 8; i++) {
            int idx = i * 32 + lane;
            int r = idx >> 4, cq = idx & 15;
            if (cq < climit) {
                int c0 = cq * 4;
                int pix = base + warp * 16 + r;
                float4 v = *(float4*)(ow + r * 68 + c0);
                float4 bv = ldg4(bias + p * 64 + c0);
                v.x += bv.x; v.y += bv.y; v.z += bv.z; v.w += bv.w;
                *(float4*)(g_om + (size_t)pix * 112 + p * 64 + c0) = v;
            }
        }
        __syncthreads();
    }
}

// ---------------- outp (K=128 -> N=128, full-N for gate) ----------------
__global__ __launch_bounds__(128) void k_mm_outp(const float* __restrict__ bias, int br) {
    const int K = 128, N = 128;
    __nv_bfloat16* a_sm = (__nv_bfloat16*)smc;
    __nv_bfloat16* b_sm = a_sm + 64 * (K + 8);
    float* out_f = (float*)smc;
    int base = blockIdx.x * 64;
    stage_A_bf16<K>(g_s, a_sm, base);
    copy_B_pad<K>(g_wbf + OFF_OUTP, b_sm, N);
    __syncthreads();
    wgemm<K, N>(a_sm, b_sm, out_f);
    int warp = threadIdx.x >> 5, lane = threadIdx.x & 31;
    float* ow = out_f + warp * 16 * 132;
    float* fo = g_feat + (size_t)br * NPIX * C0;
    #pragma unroll
    for (int i = 0; i < 8; i++) {
        int idx = i * 32 + lane;
        int r = idx >> 4, c0 = (idx & 15) * 4;
        int pix = base + warp * 16 + r;
        float4 a = *(float4*)(ow + r * 132 + c0);
        float4 b = *(float4*)(ow + r * 132 + c0 + 64);
        float4 ba = ldg4(bias + c0), bb = ldg4(bias + c0 + 64);
        float4 o;
        o.x = (a.x + ba.x) * (b.x + bb.x);
        o.y = (a.y + ba.y) * (b.y + bb.y);
        o.z = (a.z + ba.z) * (b.z + bb.z);
        o.w = (a.w + ba.w) * (b.w + bb.w);
        *(float4*)(fo + (size_t)pix * C0 + c0) = o;
    }
}

// ---------------- conv3 (K=128 -> N=64) + SE prologue + residual epilogue ----------------
__global__ __launch_bounds__(128) void k_mm_conv3(const float* __restrict__ bias,
                                                  const float* __restrict__ xl,
                                                  const float* __restrict__ xr,
                                                  const float* __restrict__ beta) {
    const int K = 128, N = 64;
    __nv_bfloat16* a_sm = (__nv_bfloat16*)smc;
    __nv_bfloat16* b_sm = a_sm + 64 * (K + 8);
    float* out_f = (float*)smc;
    int t = threadIdx.x;
    int base = blockIdx.x * 64;
    {
        int row = t >> 1, half = t & 1;
        int pix = base + row;
        int b = pix / HW;
        const float* f = g_feat + (size_t)half * NPIX * C0 + (size_t)pix * C0;
        const float* sc = g_scale + b * 128 + half * 64;
        __nv_bfloat16* d = a_sm + row * (K + 8) + half * 64;
        #pragma unroll
        for (int c = 0; c < 64; c += 8) {
            float4 v0 = *(const float4*)(f + c);
            float4 v1 = *(const float4*)(f + c + 4);
            uint4 o;
            o.x = b2u(__floats2bfloat162_rn(v0.x * sc[c], v0.y * sc[c + 1]));
            o.y = b2u(__floats2bfloat162_rn(v0.z * sc[c + 2], v0.w * sc[c + 3]));
            o.z = b2u(__floats2bfloat162_rn(v1.x * sc[c + 4], v1.y * sc[c + 5]));
            o.w = b2u(__floats2bfloat162_rn(v1.z * sc[c + 6], v1.w * sc[c + 7]));
            *(uint4*)(d + c) = o;
        }
    }
    copy_B_pad<K>(g_wbf + OFF_C3, b_sm, N);
    __syncthreads();
    wgemm<K, N>(a_sm, b_sm, out_f);
    int warp = t >> 5, lane = t & 31;
    float* ow = out_f + warp * 16 * 68;
    #pragma unroll
    for (int i = 0; i < 8; i++) {
        int idx = i * 32 + lane;
        int r = idx >> 4, c0 = (idx & 15) * 4;
        int pix = base + warp * 16 + r;
        int b = pix / HW, hw = pix % HW;
        float4 v = *(float4*)(ow + r * 68 + c0);
        float4 bv = ldg4(bias + c0), bt = ldg4(beta + c0);
        float x30 = (v.x + bv.x) * bt.x;
        float x31 = (v.y + bv.y) * bt.y;
        float x32 = (v.z + bv.z) * bt.z;
        float x33 = (v.w + bv.w) * bt.w;
        const float* xlb = xl + (size_t)b * C0 * HW + (size_t)c0 * HW + hw;
        const float* xrb = xr + (size_t)b * C0 * HW + (size_t)c0 * HW + hw;
        float4 yl, yr2;
        yl.x = xlb[0] + x30;              yl.y = xlb[(size_t)HW] + x31;
        yl.z = xlb[(size_t)2 * HW] + x32; yl.w = xlb[(size_t)3 * HW] + x33;
        yr2.x = xrb[0] + x30;              yr2.y = xrb[(size_t)HW] + x31;
        yr2.z = xrb[(size_t)2 * HW] + x32; yr2.w = xrb[(size_t)3 * HW] + x33;
        *(float4*)(g_ycat + (size_t)pix * DWC + c0) = yl;
        *(float4*)(g_ycat + (size_t)pix * DWC + 64 + c0) = yr2;
    }
}

// ---------------- LN2 + conv4 (K=128 -> N=128, full-N for gate) ----------------
__global__ __launch_bounds__(128) void k_mm_ln2c4(const float* __restrict__ g2,
                                                  const float* __restrict__ bias) {
    const int K = 128, N = 128;
    __nv_bfloat16* a_sm = (__nv_bfloat16*)smc;
    __nv_bfloat16* b_sm = a_sm + 64 * (K + 8);
    float* out_f = (float*)smc;
    int t = threadIdx.x;
    int base = blockIdx.x * 64;
    {
        int row = t >> 1, half = t & 1;
        int pix = base + row;
        const float* yr = g_ycat + (size_t)pix * DWC + half * 64;
        float v[64];
        float s1 = 0.f, s2 = 0.f;
        #pragma unroll
        for (int c = 0; c < 64; c += 4) {
            float4 a = *(const float4*)(yr + c);
            v[c] = a.x; v[c + 1] = a.y; v[c + 2] = a.z; v[c + 3] = a.w;
            s1 += a.x + a.y + a.z + a.w;
            s2 += a.x * a.x + a.y * a.y + a.z * a.z + a.w * a.w;
        }
        s1 += __shfl_xor_sync(0xffffffffu, s1, 1);
        s2 += __shfl_xor_sync(0xffffffffu, s2, 1);
        float mu = s1 * (1.f / 128.f);
        float var = s2 * (1.f / 128.f) - mu * mu;
        float rs = rsqrtf(var + 1e-5f);
        __nv_bfloat16* d = a_sm + row * (K + 8) + half * 64;
        #pragma unroll
        for (int c = 0; c < 64; c += 4) {
            float o0 = (v[c] - mu) * rs * __ldg(g2 + half * 64 + c);
            float o1 = (v[c + 1] - mu) * rs * __ldg(g2 + half * 64 + c + 1);
            float o2 = (v[c + 2] - mu) * rs * __ldg(g2 + half * 64 + c + 2);
            float o3 = (v[c + 3] - mu) * rs * __ldg(g2 + half * 64 + c + 3);
            uint2 p = make_uint2(b2u(__floats2bfloat162_rn(o0, o1)), b2u(__floats2bfloat162_rn(o2, o3)));
            *(uint2*)(d + c) = p;
        }
    }
    copy_B_pad<K>(g_wbf + OFF_C4, b_sm, N);
    __syncthreads();
    wgemm<K, N>(a_sm, b_sm, out_f);
    int warp = t >> 5, lane = t & 31;
    float* ow = out_f + warp * 16 * 132;
    #pragma unroll
    for (int i = 0; i < 8; i++) {
        int idx = i * 32 + lane;
        int r = idx >> 4, c0 = (idx & 15) * 4;
        int pix = base + warp * 16 + r;
        float4 a = *(float4*)(ow + r * 132 + c0);
        float4 b = *(float4*)(ow + r * 132 + c0 + 64);
        float4 ba = ldg4(bias + c0), bb = ldg4(bias + c0 + 64);
        float4 o;
        o.x = (a.x + ba.x) * (b.x + bb.x);
        o.y = (a.y + ba.y) * (b.y + bb.y);
        o.z = (a.z + ba.z) * (b.z + bb.z);
        o.w = (a.w + ba.w) * (b.w + bb.w);
        *(float4*)(g_g4 + (size_t)pix * C0 + c0) = o;
    }
}

// ---------------- conv5 (K=64 -> N=64) + final residuals, coalesced NCHW stores ----------------
__global__ __launch_bounds__(128) void k_mm_conv5(const float* __restrict__ bias,
                                                  const float* __restrict__ gamma,
                                                  float* __restrict__ out) {
    const int K = 64, N = 64;
    __nv_bfloat16* a_sm = (__nv_bfloat16*)smc;
    __nv_bfloat16* b_sm = a_sm + 64 * (K + 8);
    float* out_f = (float*)smc;
    int t = threadIdx.x;
    int base = blockIdx.x * 64;
    int b = base / HW, hw0 = base % HW;
    stage_A_nhwc<K>(g_g4, a_sm, base);
    copy_B_pad<K>(g_wbf + OFF_C5, b_sm, N);
    __syncthreads();
    wgemm<K, N>(a_sm, b_sm, out_f);
    // coalesced epilogue: task = (channel c, pixel-quad pq)
    #pragma unroll
    for (int i = 0; i < 8; i++) {
        int idx = i * 128 + t;
        int c = idx >> 4, pq = idx & 15;
        float bc = __ldg(bias + c), gc = __ldg(gamma + c);
        float4 vl, vr;
        #pragma unroll
        for (int j = 0; j < 4; j++) {
            int r = pq * 4 + j;
            float z = (out_f[r * 68 + c] + bc) * gc;
            int pix = base + r;
            float ycl = g_ycat[(size_t)pix * DWC + c];
            float ycr = g_ycat[(size_t)pix * DWC + 64 + c];
            ((float*)&vl)[j] = ycl + z;
            ((float*)&vr)[j] = ycr + z;
        }
        float* o0 = out + (size_t)b * C0 * HW + (size_t)c * HW + hw0 + pq * 4;
        *(float4*)o0 = vl;
        *(float4*)(o0 + (size_t)NOUT) = vr;
    }
}

// ---------------- non-GEMM kernels ----------------
__global__ void k_zero_vp() {
    size_t i = (size_t)blockIdx.x * 256 + threadIdx.x;
    size_t n16 = (size_t)BB * HP * WP * DWC * 2 / 16;
    if (i < n16) reinterpret_cast<uint4*>(g_vp)[i] = make_uint4(0u, 0u, 0u, 0u);
}

__device__ __forceinline__ void fma8(uint4 h, uint4 w, float* acc) {
    const __nv_bfloat162* hp = (const __nv_bfloat162*)&h;
    const __nv_bfloat162* wp = (const __nv_bfloat162*)&w;
    #pragma unroll
    for (int q = 0; q < 4; q++) {
        float2 hf = __bfloat1622float2(hp[q]);
        float2 wf = __bfloat1622float2(wp[q]);
        acc[2 * q]     = fmaf(hf.x, wf.x, acc[2 * q]);
        acc[2 * q + 1] = fmaf(hf.y, wf.y, acc[2 * q + 1]);
    }
}

__global__ __launch_bounds__(256) void k_dwc(const float* __restrict__ bias) {
    int tid = blockIdx.x * 256 + threadIdx.x;
    if (tid >= NPIX * 16) return;
    int c8 = (tid & 15) * 8;
    int pix = tid >> 4;
    int b = pix / HW, hw = pix % HW;
    int y = hw / WW, x = hw % WW;
    float acc[8];
    {
        float4 b0 = ldg4(bias + c8), b1 = ldg4(bias + c8 + 4);
        acc[0] = b0.x; acc[1] = b0.y; acc[2] = b0.z; acc[3] = b0.w;
        acc[4] = b1.x; acc[5] = b1.y; acc[6] = b1.z; acc[7] = b1.w;
    }
    #pragma unroll
    for (int ky = 0; ky < 3; ky++) {
        int yy = y + ky - 1;
        if (yy < 0 || yy >= HH) continue;
        #pragma unroll
        for (int kx = 0; kx < 3; kx++) {
            int xx = x + kx - 1;
            if (xx < 0 || xx >= WW) continue;
            uint4 hv = *(const uint4*)(g_h + ((size_t)b * HW + (size_t)yy * WW + xx) * DWC + c8);
            uint4 wv = *(const uint4*)(g_wbf + OFF_DWC + (ky * 3 + kx) * DWC + c8);
            fma8(hv, wv, acc);
        }
    }
    uint4 o;
    o.x = b2u(__floats2bfloat162_rn(acc[0], acc[1]));
    o.y = b2u(__floats2bfloat162_rn(acc[2], acc[3]));
    o.z = b2u(__floats2bfloat162_rn(acc[4], acc[5]));
    o.w = b2u(__floats2bfloat162_rn(acc[6], acc[7]));
    *(uint4*)(g_dw + (size_t)pix * DWC + c8) = o;
}

__global__ __launch_bounds__(256) void k_sample() {
    __shared__ float som[224];
    int t = threadIdx.x;
    int base = blockIdx.x * 2;
    for (int i = t; i < 224; i += 256) som[i] = g_om[(size_t)base * 112 + i];
    __syncthreads();
    int wp = t >> 5, lane = t & 31;
    int pi = wp >> 2, g = wp & 3;
    int pix = base + pi;
    int b = pix / HW, hw = pix % HW;
    int y = hw / WW, x = hw % WW;
    const float* om = som + pi * 112 + g * 27;
    int gc = g * 32 + lane;
    const __nv_bfloat16* vpb = g_vp + (size_t)b * HP * WP * DWC + gc;
    float acc = 0.f;
    #pragma unroll
    for (int k = 0; k < 9; k++) {
        float offx = om[k * 3 + 0];
        float offy = om[k * 3 + 1];
        float mask = om[k * 3 + 2];
        float px = (float)(x + (k % 3)) + offx;
        float py = (float)(y + (k / 3)) + offy;
        float x0f = floorf(px), y0f = floorf(py);
        float tx = px - x0f, ty = py - y0f;
        int x0 = (int)x0f, y0 = (int)y0f;
        #pragma unroll
        for (int dy = 0; dy < 2; dy++) {
            #pragma unroll
            for (int dx = 0; dx < 2; dx++) {
                int xi = x0 + dx, yi = y0 + dy;
                float wg = (dx ? tx : 1.f - tx) * (dy ? ty : 1.f - ty);
                bool valid = (xi >= 0) & (xi < WP) & (yi >= 0) & (yi < HP);
                wg = valid ? wg * mask : 0.f;
                int xc = min(max(xi, 0), WP - 1);
                int yc = min(max(yi, 0), HP - 1);
                acc = fmaf(wg, __bfloat162float(vpb[((size_t)yc * WP + xc) * DWC]), acc);
            }
        }
    }
    g_s[(size_t)pix * DWC + gc] = __float2bfloat16(acc);
}

__global__ __launch_bounds__(256) void k_pool1() {
    __shared__ float red[256];
    int blk = blockIdx.x;
    int chunk = blk % 100;
    int bb = (blk / 100) & 1;
    int br = blk / 200;
    int pix0 = bb * HW + chunk * 256;
    int c = threadIdx.x & 63, sub = threadIdx.x >> 6;
    const float* f = g_feat + (size_t)br * NPIX * C0 + (size_t)(pix0 + sub * 64) * C0 + c;
    float s = 0.f;
    #pragma unroll 4
    for (int p = 0; p < 64; p++) s += f[(size_t)p * C0];
    red[threadIdx.x] = s;
    __syncthreads();
    if (sub == 0)
        g_part[blk * 64 + c] = red[c] + red[64 + c] + red[128 + c] + red[192 + c];
}

__global__ __launch_bounds__(256) void k_pool_scale(const float* __restrict__ sw,
                                                    const float* __restrict__ sb) {
    __shared__ float pooled[2 * 128];
    int t = threadIdx.x;
    int b = t >> 7, cc = t & 127;
    int br = cc >> 6, c = cc & 63;
    float s = 0.f;
    for (int ch = 0; ch < 100; ch++)
        s += g_part[((br * 2 + b) * 100 + ch) * 64 + c];
    pooled[b * 128 + cc] = s * (1.f / (float)HW);
    __syncthreads();
    float acc = sb[cc];
    #pragma unroll 4
    for (int k = 0; k < 128; k++) acc = fmaf(sw[cc * 128 + k], pooled[b * 128 + k], acc);
    g_scale[b * 128 + cc] = acc;
}

// ---------------- host launch ----------------
extern "C" void kernel_launch(void* const* d_in, const int* in_sizes, int n_in,
                              void* d_out, int out_size) {
    const float* x_l     = (const float*)d_in[0];
    const float* x_r     = (const float*)d_in[1];
    const float* ln1_g   = (const float*)d_in[2];
    const float* pw1_w   = (const float*)d_in[3];
    const float* pw1_b   = (const float*)d_in[4];
    const float* val_w   = (const float*)d_in[5];
    const float* val_b   = (const float*)d_in[6];
    const float* dwc_w   = (const float*)d_in[7];
    const float* dwc_b   = (const float*)d_in[8];
    const float* om_w    = (const float*)d_in[9];
    const float* om_b    = (const float*)d_in[10];
    const float* outp_w  = (const float*)d_in[11];
    const float* outp_b  = (const float*)d_in[12];
    const float* sca_w   = (const float*)d_in[13];
    const float* sca_b   = (const float*)d_in[14];
    const float* conv3_w = (const float*)d_in[15];
    const float* conv3_b = (const float*)d_in[16];
    const float* norm2_g = (const float*)d_in[17];
    const float* conv4_w = (const float*)d_in[18];
    const float* conv4_b = (const float*)d_in[19];
    const float* conv5_w = (const float*)d_in[20];
    const float* conv5_b = (const float*)d_in[21];
    const float* beta    = (const float*)d_in[22];
    const float* gamma   = (const float*)d_in[23];
    float* out = (float*)d_out;

    const int SM_PW1  = 64 * 132 * 4;                 // 33792 (out alias covers A+B=27648)
    const int SM_VAL  = 17408 + 17408;                // 34816 (A + B/out union)
    const int SM_OM   = SM_VAL;
    const int SM_OUTP = 64 * 136 * 2 + 128 * 136 * 2; // 52224
    const int SM_C3   = 64 * 136 * 2 + 64 * 136 * 2;  // 34816
    const int SM_C4   = SM_OUTP;
    const int SM_C5   = 64 * 72 * 2 + 64 * 72 * 2;    // 18432

    cudaFuncSetAttribute(k_mm_pw1,   cudaFuncAttributeMaxDynamicSharedMemorySize, SM_PW1);
    cudaFuncSetAttribute(k_mm_val,   cudaFuncAttributeMaxDynamicSharedMemorySize, SM_VAL);
    cudaFuncSetAttribute(k_mm_om,    cudaFuncAttributeMaxDynamicSharedMemorySize, SM_OM);
    cudaFuncSetAttribute(k_mm_outp,  cudaFuncAttributeMaxDynamicSharedMemorySize, SM_OUTP);
    cudaFuncSetAttribute(k_mm_conv3, cudaFuncAttributeMaxDynamicSharedMemorySize, SM_C3);
    cudaFuncSetAttribute(k_mm_ln2c4, cudaFuncAttributeMaxDynamicSharedMemorySize, SM_C4);
    cudaFuncSetAttribute(k_mm_conv5, cudaFuncAttributeMaxDynamicSharedMemorySize, SM_C5);

    const int NBM = NPIX / 64;  // 800

    k_prep_w<<<dim3(64, 8), 256>>>(pw1_w, val_w, om_w, outp_w, conv3_w, conv4_w, conv5_w, dwc_w);
    k_zero_vp<<<3281, 256>>>();

    for (int br = 0; br < 2; br++) {
        const float* x = br ? x_r : x_l;
        k_mm_pw1<<<NBM, 128, SM_PW1>>>(x, ln1_g, pw1_b);
        k_mm_val<<<NBM, 128, SM_VAL>>>(val_b);
        k_dwc<<<NPIX * 16 / 256, 256>>>(dwc_b);
        k_mm_om<<<NBM, 128, SM_OM>>>(om_b);
        k_sample<<<NPIX / 2, 256>>>();
        k_mm_outp<<<NBM, 128, SM_OUTP>>>(outp_b, br);
    }

    k_pool1<<<400, 256>>>();
    k_pool_scale<<<1, 256>>>(sca_w, sca_b);
    k_mm_conv3<<<NBM, 128, SM_C3>>>(conv3_b, x_l, x_r, beta);
    k_mm_ln2c4<<<NBM, 128, SM_C4>>>(norm2_g, conv4_b);
    k_mm_conv5<<<NBM, 128, SM_C5>>>(conv5_b, gamma, out);
}

// round 17
// speedup vs baseline: 2.2609x; 1.3959x over previous
#include <cuda_runtime.h>
#include <cuda_bf16.h>
#include <mma.h>
#include <cstdint>
#include <stdint.h>
#include <math.h>
#include <string.h>

using namespace nvcuda;

#define BB 2
#define C0 64
#define DWC 128
#define HH 160
#define WW 160
#define HW (HH*WW)
#define NPIX (BB*HW)
#define HP 162
#define WP 162
#define NOUT (BB*C0*HW)

// plain bf16 weight tiles [oc][cin] (element offsets)
#define OFF_PW1  0
#define OFF_VAL  8192
#define OFF_OM   24576
#define OFF_OUTP 40960
#define OFF_C3   57344
#define OFF_C4   65536
#define OFF_C5   81920
#define OFF_DWC  86016
#define WBF_TOT  87168

// ---------------- scratch ----------------
__device__ __nv_bfloat16 g_h[(size_t)NPIX*DWC];
__device__ __nv_bfloat16 g_vp[(size_t)BB*HP*WP*DWC];
__device__ __nv_bfloat16 g_dw[(size_t)NPIX*DWC];
__device__ float g_om[(size_t)NPIX*112];
__device__ __nv_bfloat16 g_s[(size_t)NPIX*DWC];
__device__ float g_feat[(size_t)2*NPIX*C0];
__device__ float g_g4[(size_t)NPIX*C0];
__device__ float g_part[400*64];
__device__ float g_scale[BB*DWC];
__device__ float g_ycat[(size_t)NPIX*DWC];
__device__ __nv_bfloat16 g_wbf[WBF_TOT];

extern __shared__ __align__(16) char smc[];

__device__ __forceinline__ uint32_t b2u(__nv_bfloat162 h) { uint32_t u; memcpy(&u, &h, 4); return u; }
__device__ __forceinline__ float4 ldg4(const float* p) { return *(const float4*)p; }

// ---------------- staging helpers (128-thread CTA) ----------------
template<int K>
__device__ __forceinline__ void copy_B_pad(const __nv_bfloat16* gw, __nv_bfloat16* b_sm, int N) {
    const int SEGS = K / 8;
    for (int i = threadIdx.x; i < N * SEGS; i += 128) {
        int row = i / SEGS, seg = i - row * SEGS;
        uint4 v = ((const uint4*)gw)[i];
        *(uint4*)(b_sm + row * (K + 8) + seg * 8) = v;
    }
}
// A: NHWC fp32 -> smem bf16 [64][K+8]
template<int K>
__device__ __forceinline__ void stage_A_nhwc(const float* __restrict__ src, __nv_bfloat16* a_sm, int base) {
    int row = threadIdx.x >> 1, half = threadIdx.x & 1;
    const float* s = src + (size_t)(base + row) * K + half * (K / 2);
    __nv_bfloat16* d = a_sm + row * (K + 8) + half * (K / 2);
    #pragma unroll
    for (int k = 0; k < K / 2; k += 8) {
        float4 v0 = *(const float4*)(s + k);
        float4 v1 = *(const float4*)(s + k + 4);
        uint4 o;
        o.x = b2u(__floats2bfloat162_rn(v0.x, v0.y));
        o.y = b2u(__floats2bfloat162_rn(v0.z, v0.w));
        o.z = b2u(__floats2bfloat162_rn(v1.x, v1.y));
        o.w = b2u(__floats2bfloat162_rn(v1.z, v1.w));
        *(uint4*)(d + k) = o;
    }
}
// A: NHWC bf16 -> smem pure copy [64][K+8]
template<int K>
__device__ __forceinline__ void stage_A_bf16(const __nv_bfloat16* __restrict__ src, __nv_bfloat16* a_sm, int base) {
    int row = threadIdx.x >> 1, half = threadIdx.x & 1;
    const uint4* s = (const uint4*)(src + (size_t)(base + row) * K + half * (K / 2));
    uint4* d = (uint4*)(a_sm + row * (K + 8) + half * (K / 2));
    #pragma unroll
    for (int k = 0; k < K / 16; k++) d[k] = s[k];
}

// ---------------- full-N wgemm (M=64, 4 warps), out aliases smc start ----------------
template<int K, int N>
__device__ __forceinline__ void wgemm(const __nv_bfloat16* a_sm, const __nv_bfloat16* b_sm, float* out_f) {
    const int warp = threadIdx.x >> 5;
    const int LDA = K + 8, LDO = N + 4;
    wmma::fragment<wmma::accumulator, 16, 16, 16, float> acc[N / 16];
    #pragma unroll
    for (int n = 0; n < N / 16; n++) wmma::fill_fragment(acc[n], 0.f);
    #pragma unroll
    for (int k = 0; k < K; k += 16) {
        wmma::fragment<wmma::matrix_a, 16, 16, 16, __nv_bfloat16, wmma::row_major> af;
        wmma::load_matrix_sync(af, a_sm + warp * 16 * LDA + k, LDA);
        #pragma unroll
        for (int n = 0; n < N / 16; n++) {
            wmma::fragment<wmma::matrix_b, 16, 16, 16, __nv_bfloat16, wmma::col_major> bf;
            wmma::load_matrix_sync(bf, b_sm + n * 16 * LDA + k, LDA);
            wmma::mma_sync(acc[n], af, bf, acc[n]);
        }
    }
    __syncthreads();
    float* ow = out_f + warp * 16 * LDO;
    #pragma unroll
    for (int n = 0; n < N / 16; n++)
        wmma::store_matrix_sync(ow + n * 16, acc[n], LDO, wmma::mem_row_major);
}

// ---------------- half-N wgemm (N=64 pass), out aliases the B region ----------------
template<int K>
__device__ __forceinline__ void wgemm64(const __nv_bfloat16* a_sm, const __nv_bfloat16* b_sm, float* out_f) {
    const int warp = threadIdx.x >> 5;
    const int LDA = K + 8, LDO = 68;
    wmma::fragment<wmma::accumulator, 16, 16, 16, float> acc[4];
    #pragma unroll
    for (int n = 0; n < 4; n++) wmma::fill_fragment(acc[n], 0.f);
    #pragma unroll
    for (int k = 0; k < K; k += 16) {
        wmma::fragment<wmma::matrix_a, 16, 16, 16, __nv_bfloat16, wmma::row_major> af;
        wmma::load_matrix_sync(af, a_sm + warp * 16 * LDA + k, LDA);
        #pragma unroll
        for (int n = 0; n < 4; n++) {
            wmma::fragment<wmma::matrix_b, 16, 16, 16, __nv_bfloat16, wmma::col_major> bf;
            wmma::load_matrix_sync(bf, b_sm + n * 16 * LDA + k, LDA);
            wmma::mma_sync(acc[n], af, bf, acc[n]);
        }
    }
    __syncthreads();   // all mma reads of B done before overwrite with out
    float* ow = out_f + warp * 16 * LDO;
    #pragma unroll
    for (int n = 0; n < 4; n++)
        wmma::store_matrix_sync(ow + n * 16, acc[n], LDO, wmma::mem_row_major);
}

// ---------------- weight prep ----------------
__global__ __launch_bounds__(256) void k_prep_w(
    const float* __restrict__ pw1_w, const float* __restrict__ val_w,
    const float* __restrict__ om_w, const float* __restrict__ outp_w,
    const float* __restrict__ c3_w, const float* __restrict__ c4_w,
    const float* __restrict__ c5_w, const float* __restrict__ dwc_w)
{
    int m = blockIdx.y;
    int N, K, rows, base;
    const float* src;
    switch (m) {
        case 0: N = 128; K = 64;  rows = 128; base = OFF_PW1;  src = pw1_w;  break;
        case 1: N = 128; K = 128; rows = 128; base = OFF_VAL;  src = val_w;  break;
        case 2: N = 128; K = 128; rows = 112; base = OFF_OM;   src = om_w;   break;
        case 3: N = 128; K = 128; rows = 128; base = OFF_OUTP; src = outp_w; break;
        case 4: N = 64;  K = 128; rows = 64;  base = OFF_C3;   src = c3_w;   break;
        case 5: N = 128; K = 128; rows = 128; base = OFF_C4;   src = c4_w;   break;
        case 6: N = 64;  K = 64;  rows = 64;  base = OFF_C5;   src = c5_w;   break;
        default:N = 9;   K = 128; rows = 9;   base = OFF_DWC;  src = dwc_w;  break;
    }
    int idx = blockIdx.x * 256 + threadIdx.x;
    if (idx >= N * K) return;
    int row = idx / K;
    float v = (row < rows) ? src[idx] : 0.f;
    g_wbf[base + idx] = __float2bfloat16(v);
}

// ---------------- LN1 + pw1 (K=64 -> N=128), coalesced x load, col-major A ----------------
__global__ __launch_bounds__(128) void k_mm_pw1(const float* __restrict__ x,
                                                const float* __restrict__ g,
                                                const float* __restrict__ bias) {
    const int K = 64, N = 128;
    const int LDA = 72;
    __nv_bfloat16* a_sm = (__nv_bfloat16*)smc;
    __nv_bfloat16* b_sm = a_sm + 64 * LDA;
    float* out_f = (float*)smc;
    int t = threadIdx.x;
    int base = blockIdx.x * 64;
    int b = base / HW, hw0 = base % HW;
    const float* xb = x + (size_t)b * C0 * HW + hw0;
    #pragma unroll
    for (int i = 0; i < 8; i++) {
        int idx = i * 128 + t;
        int c = idx >> 4, pq = idx & 15;
        float4 v = *(const float4*)(xb + (size_t)c * HW + pq * 4);
        uint2 p = make_uint2(b2u(__floats2bfloat162_rn(v.x, v.y)), b2u(__floats2bfloat162_rn(v.z, v.w)));
        *(uint2*)(a_sm + c * LDA + pq * 4) = p;
    }
    copy_B_pad<K>(g_wbf + OFF_PW1, b_sm, N);
    __syncthreads();
    {
        int pix = t >> 1, half = t & 1;
        float vv[32];
        float s1 = 0.f, s2 = 0.f;
        #pragma unroll
        for (int i = 0; i < 32; i++) {
            float v = __bfloat162float(a_sm[(half * 32 + i) * LDA + pix]);
            vv[i] = v; s1 += v; s2 += v * v;
        }
        s1 += __shfl_xor_sync(0xffffffffu, s1, 1);
        s2 += __shfl_xor_sync(0xffffffffu, s2, 1);
        float mu = s1 * (1.f / 64.f);
        float var = s2 * (1.f / 64.f) - mu * mu;
        float r = rsqrtf(var + 1e-5f);
        #pragma unroll
        for (int i = 0; i < 32; i++)
            a_sm[(half * 32 + i) * LDA + pix] = __float2bfloat16((vv[i] - mu) * r * __ldg(g + half * 32 + i));
    }
    __syncthreads();
    {
        const int warp = t >> 5;
        wmma::fragment<wmma::accumulator, 16, 16, 16, float> acc[8];
        #pragma unroll
        for (int n = 0; n < 8; n++) wmma::fill_fragment(acc[n], 0.f);
        #pragma unroll
        for (int k = 0; k < K; k += 16) {
            wmma::fragment<wmma::matrix_a, 16, 16, 16, __nv_bfloat16, wmma::col_major> af;
            wmma::load_matrix_sync(af, a_sm + k * LDA + warp * 16, LDA);
            #pragma unroll
            for (int n = 0; n < 8; n++) {
                wmma::fragment<wmma::matrix_b, 16, 16, 16, __nv_bfloat16, wmma::col_major> bf;
                wmma::load_matrix_sync(bf, b_sm + n * 16 * LDA + k, LDA);
                wmma::mma_sync(acc[n], af, bf, acc[n]);
            }
        }
        __syncthreads();
        float* ow = out_f + warp * 16 * 132;
        #pragma unroll
        for (int n = 0; n < 8; n++)
            wmma::store_matrix_sync(ow + n * 16, acc[n], 132, wmma::mem_row_major);
    }
    int warp = t >> 5, lane = t & 31;
    float* ow = out_f + warp * 16 * 132;
    int c0 = lane * 4;
    float4 bv = ldg4(bias + c0);
    #pragma unroll
    for (int r = 0; r < 16; r++) {
        int pix = base + warp * 16 + r;
        float4 v = *(float4*)(ow + r * 132 + c0);
        v.x += bv.x; v.y += bv.y; v.z += bv.z; v.w += bv.w;
        uint2 p = make_uint2(b2u(__floats2bfloat162_rn(v.x, v.y)), b2u(__floats2bfloat162_rn(v.z, v.w)));
        *(uint2*)(g_h + (size_t)pix * DWC + c0) = p;
    }
}

// ---------------- val (K=128 -> N=128, two N=64 passes) ----------------
__global__ __launch_bounds__(128) void k_mm_val(const float* __restrict__ bias) {
    const int K = 128;
    __nv_bfloat16* a_sm = (__nv_bfloat16*)smc;
    __nv_bfloat16* b_sm = (__nv_bfloat16*)(smc + 17408);
    float* out_f = (float*)(smc + 17408);
    int base = blockIdx.x * 64;
    int warp = threadIdx.x >> 5, lane = threadIdx.x & 31;
    stage_A_bf16<K>(g_h, a_sm, base);
    #pragma unroll
    for (int p = 0; p < 2; p++) {
        copy_B_pad<K>(g_wbf + OFF_VAL + p * 64 * K, b_sm, 64);
        __syncthreads();
        wgemm64<K>(a_sm, b_sm, out_f);
        float* ow = out_f + warp * 16 * 68;
        #pragma unroll
        for (int i = 0; i < 8; i++) {
            int idx = i * 32 + lane;
            int r = idx >> 4, c0 = (idx & 15) * 4;
            int pix = base + warp * 16 + r;
            int b = pix / HW, hw = pix % HW;
            int y = hw / WW, xx = hw % WW;
            float4 v = *(float4*)(ow + r * 68 + c0);
            float4 bv = ldg4(bias + p * 64 + c0);
            v.x += bv.x; v.y += bv.y; v.z += bv.z; v.w += bv.w;
            uint2 o = make_uint2(b2u(__floats2bfloat162_rn(v.x, v.y)), b2u(__floats2bfloat162_rn(v.z, v.w)));
            *(uint2*)(g_vp + ((size_t)(b * HP + y + 1) * WP + (xx + 1)) * DWC + p * 64 + c0) = o;
        }
        __syncthreads();
    }
}

// ---------------- om (K=128 -> N=112, two passes) ----------------
__global__ __launch_bounds__(128) void k_mm_om(const float* __restrict__ bias) {
    const int K = 128;
    __nv_bfloat16* a_sm = (__nv_bfloat16*)smc;
    __nv_bfloat16* b_sm = (__nv_bfloat16*)(smc + 17408);
    float* out_f = (float*)(smc + 17408);
    int base = blockIdx.x * 64;
    int warp = threadIdx.x >> 5, lane = threadIdx.x & 31;
    stage_A_bf16<K>(g_dw, a_sm, base);
    #pragma unroll
    for (int p = 0; p < 2; p++) {
        copy_B_pad<K>(g_wbf + OFF_OM + p * 64 * K, b_sm, 64);
        __syncthreads();
        wgemm64<K>(a_sm, b_sm, out_f);
        float* ow = out_f + warp * 16 * 68;
        int climit = p ? 12 : 16;
        #pragma unroll
        for (int i = 0; i < 8; i++) {
            int idx = i * 32 + lane;
            int r = idx >> 4, cq = idx & 15;
            if (cq < climit) {
                int c0 = cq * 4;
                int pix = base + warp * 16 + r;
                float4 v = *(float4*)(ow + r * 68 + c0);
                float4 bv = ldg4(bias + p * 64 + c0);
                v.x += bv.x; v.y += bv.y; v.z += bv.z; v.w += bv.w;
                *(float4*)(g_om + (size_t)pix * 112 + p * 64 + c0) = v;
            }
        }
        __syncthreads();
    }
}

// ---------------- outp (K=128 -> N=128, full-N for gate) ----------------
__global__ __launch_bounds__(128) void k_mm_outp(const float* __restrict__ bias, int br) {
    const int K = 128, N = 128;
    __nv_bfloat16* a_sm = (__nv_bfloat16*)smc;
    __nv_bfloat16* b_sm = a_sm + 64 * (K + 8);
    float* out_f = (float*)smc;
    int base = blockIdx.x * 64;
    stage_A_bf16<K>(g_s, a_sm, base);
    copy_B_pad<K>(g_wbf + OFF_OUTP, b_sm, N);
    __syncthreads();
    wgemm<K, N>(a_sm, b_sm, out_f);
    int warp = threadIdx.x >> 5, lane = threadIdx.x & 31;
    float* ow = out_f + warp * 16 * 132;
    float* fo = g_feat + (size_t)br * NPIX * C0;
    #pragma unroll
    for (int i = 0; i < 8; i++) {
        int idx = i * 32 + lane;
        int r = idx >> 4, c0 = (idx & 15) * 4;
        int pix = base + warp * 16 + r;
        float4 a = *(float4*)(ow + r * 132 + c0);
        float4 b = *(float4*)(ow + r * 132 + c0 + 64);
        float4 ba = ldg4(bias + c0), bb = ldg4(bias + c0 + 64);
        float4 o;
        o.x = (a.x + ba.x) * (b.x + bb.x);
        o.y = (a.y + ba.y) * (b.y + bb.y);
        o.z = (a.z + ba.z) * (b.z + bb.z);
        o.w = (a.w + ba.w) * (b.w + bb.w);
        *(float4*)(fo + (size_t)pix * C0 + c0) = o;
    }
}

// ---------------- conv3 (K=128 -> N=64) + SE prologue + residual epilogue ----------------
__global__ __launch_bounds__(128) void k_mm_conv3(const float* __restrict__ bias,
                                                  const float* __restrict__ xl,
                                                  const float* __restrict__ xr,
                                                  const float* __restrict__ beta) {
    const int K = 128, N = 64;
    __nv_bfloat16* a_sm = (__nv_bfloat16*)smc;
    __nv_bfloat16* b_sm = a_sm + 64 * (K + 8);
    float* out_f = (float*)smc;
    int t = threadIdx.x;
    int base = blockIdx.x * 64;
    {
        int row = t >> 1, half = t & 1;
        int pix = base + row;
        int b = pix / HW;
        const float* f = g_feat + (size_t)half * NPIX * C0 + (size_t)pix * C0;
        const float* sc = g_scale + b * 128 + half * 64;
        __nv_bfloat16* d = a_sm + row * (K + 8) + half * 64;
        #pragma unroll
        for (int c = 0; c < 64; c += 8) {
            float4 v0 = *(const float4*)(f + c);
            float4 v1 = *(const float4*)(f + c + 4);
            uint4 o;
            o.x = b2u(__floats2bfloat162_rn(v0.x * sc[c], v0.y * sc[c + 1]));
            o.y = b2u(__floats2bfloat162_rn(v0.z * sc[c + 2], v0.w * sc[c + 3]));
            o.z = b2u(__floats2bfloat162_rn(v1.x * sc[c + 4], v1.y * sc[c + 5]));
            o.w = b2u(__floats2bfloat162_rn(v1.z * sc[c + 6], v1.w * sc[c + 7]));
            *(uint4*)(d + c) = o;
        }
    }
    copy_B_pad<K>(g_wbf + OFF_C3, b_sm, N);
    __syncthreads();
    wgemm<K, N>(a_sm, b_sm, out_f);
    int warp = t >> 5, lane = t & 31;
    float* ow = out_f + warp * 16 * 68;
    #pragma unroll
    for (int i = 0; i < 8; i++) {
        int idx = i * 32 + lane;
        int r = idx >> 4, c0 = (idx & 15) * 4;
        int pix = base + warp * 16 + r;
        int b = pix / HW, hw = pix % HW;
        float4 v = *(float4*)(ow + r * 68 + c0);
        float4 bv = ldg4(bias + c0), bt = ldg4(beta + c0);
        float x30 = (v.x + bv.x) * bt.x;
        float x31 = (v.y + bv.y) * bt.y;
        float x32 = (v.z + bv.z) * bt.z;
        float x33 = (v.w + bv.w) * bt.w;
        const float* xlb = xl + (size_t)b * C0 * HW + (size_t)c0 * HW + hw;
        const float* xrb = xr + (size_t)b * C0 * HW + (size_t)c0 * HW + hw;
        float4 yl, yr2;
        yl.x = xlb[0] + x30;              yl.y = xlb[(size_t)HW] + x31;
        yl.z = xlb[(size_t)2 * HW] + x32; yl.w = xlb[(size_t)3 * HW] + x33;
        yr2.x = xrb[0] + x30;              yr2.y = xrb[(size_t)HW] + x31;
        yr2.z = xrb[(size_t)2 * HW] + x32; yr2.w = xrb[(size_t)3 * HW] + x33;
        *(float4*)(g_ycat + (size_t)pix * DWC + c0) = yl;
        *(float4*)(g_ycat + (size_t)pix * DWC + 64 + c0) = yr2;
    }
}

// ---------------- LN2 + conv4 (K=128 -> N=128, full-N for gate) ----------------
__global__ __launch_bounds__(128) void k_mm_ln2c4(const float* __restrict__ g2,
                                                  const float* __restrict__ bias) {
    const int K = 128, N = 128;
    __nv_bfloat16* a_sm = (__nv_bfloat16*)smc;
    __nv_bfloat16* b_sm = a_sm + 64 * (K + 8);
    float* out_f = (float*)smc;
    int t = threadIdx.x;
    int base = blockIdx.x * 64;
    {
        int row = t >> 1, half = t & 1;
        int pix = base + row;
        const float* yr = g_ycat + (size_t)pix * DWC + half * 64;
        float v[64];
        float s1 = 0.f, s2 = 0.f;
        #pragma unroll
        for (int c = 0; c < 64; c += 4) {
            float4 a = *(const float4*)(yr + c);
            v[c] = a.x; v[c + 1] = a.y; v[c + 2] = a.z; v[c + 3] = a.w;
            s1 += a.x + a.y + a.z + a.w;
            s2 += a.x * a.x + a.y * a.y + a.z * a.z + a.w * a.w;
        }
        s1 += __shfl_xor_sync(0xffffffffu, s1, 1);
        s2 += __shfl_xor_sync(0xffffffffu, s2, 1);
        float mu = s1 * (1.f / 128.f);
        float var = s2 * (1.f / 128.f) - mu * mu;
        float rs = rsqrtf(var + 1e-5f);
        __nv_bfloat16* d = a_sm + row * (K + 8) + half * 64;
        #pragma unroll
        for (int c = 0; c < 64; c += 4) {
            float o0 = (v[c] - mu) * rs * __ldg(g2 + half * 64 + c);
            float o1 = (v[c + 1] - mu) * rs * __ldg(g2 + half * 64 + c + 1);
            float o2 = (v[c + 2] - mu) * rs * __ldg(g2 + half * 64 + c + 2);
            float o3 = (v[c + 3] - mu) * rs * __ldg(g2 + half * 64 + c + 3);
            uint2 p = make_uint2(b2u(__floats2bfloat162_rn(o0, o1)), b2u(__floats2bfloat162_rn(o2, o3)));
            *(uint2*)(d + c) = p;
        }
    }
    copy_B_pad<K>(g_wbf + OFF_C4, b_sm, N);
    __syncthreads();
    wgemm<K, N>(a_sm, b_sm, out_f);
    int warp = t >> 5, lane = t & 31;
    float* ow = out_f + warp * 16 * 132;
    #pragma unroll
    for (int i = 0; i < 8; i++) {
        int idx = i * 32 + lane;
        int r = idx >> 4, c0 = (idx & 15) * 4;
        int pix = base + warp * 16 + r;
        float4 a = *(float4*)(ow + r * 132 + c0);
        float4 b = *(float4*)(ow + r * 132 + c0 + 64);
        float4 ba = ldg4(bias + c0), bb = ldg4(bias + c0 + 64);
        float4 o;
        o.x = (a.x + ba.x) * (b.x + bb.x);
        o.y = (a.y + ba.y) * (b.y + bb.y);
        o.z = (a.z + ba.z) * (b.z + bb.z);
        o.w = (a.w + ba.w) * (b.w + bb.w);
        *(float4*)(g_g4 + (size_t)pix * C0 + c0) = o;
    }
}

// ---------------- conv5 (K=64 -> N=64) + final residuals, coalesced NCHW stores ----------------
__global__ __launch_bounds__(128) void k_mm_conv5(const float* __restrict__ bias,
                                                  const float* __restrict__ gamma,
                                                  float* __restrict__ out) {
    const int K = 64, N = 64;
    __nv_bfloat16* a_sm = (__nv_bfloat16*)smc;
    __nv_bfloat16* b_sm = a_sm + 64 * (K + 8);
    float* out_f = (float*)smc;
    int t = threadIdx.x;
    int base = blockIdx.x * 64;
    int b = base / HW, hw0 = base % HW;
    stage_A_nhwc<K>(g_g4, a_sm, base);
    copy_B_pad<K>(g_wbf + OFF_C5, b_sm, N);
    __syncthreads();
    wgemm<K, N>(a_sm, b_sm, out_f);
    #pragma unroll
    for (int i = 0; i < 8; i++) {
        int idx = i * 128 + t;
        int c = idx >> 4, pq = idx & 15;
        float bc = __ldg(bias + c), gc = __ldg(gamma + c);
        float4 vl, vr;
        #pragma unroll
        for (int j = 0; j < 4; j++) {
            int r = pq * 4 + j;
            float z = (out_f[r * 68 + c] + bc) * gc;
            int pix = base + r;
            float ycl = g_ycat[(size_t)pix * DWC + c];
            float ycr = g_ycat[(size_t)pix * DWC + 64 + c];
            ((float*)&vl)[j] = ycl + z;
            ((float*)&vr)[j] = ycr + z;
        }
        float* o0 = out + (size_t)b * C0 * HW + (size_t)c * HW + hw0 + pq * 4;
        *(float4*)o0 = vl;
        *(float4*)(o0 + (size_t)NOUT) = vr;
    }
}

// ---------------- zero only the PAD BORDER of g_vp (interior is fully overwritten by val) ----------------
__global__ __launch_bounds__(256) void k_zero_vp_border() {
    // per batch: 644 border pixels (y=0 row, y=161 row, x=0 col, x=161 col), 128 ch each
    // thread handles 16 channels (one uint4 of bf16x8? 16ch*2B=32B = 2 uint4) -> use 8 ch (16B)
    int tid = blockIdx.x * 256 + threadIdx.x;
    int total = BB * 644 * 16;            // 16 chunks of 8 ch per pixel
    if (tid >= total) return;
    int chunk = tid & 15;
    int pi = tid >> 4;
    int b = pi / 644, j = pi % 644;
    int y, x;
    if (j < 162)      { y = 0;       x = j; }
    else if (j < 324) { y = 161;     x = j - 162; }
    else if (j < 484) { x = 0;       y = j - 324 + 1; }
    else              { x = 161;     y = j - 484 + 1; }
    *(uint4*)(g_vp + ((size_t)(b * HP + y) * WP + x) * DWC + chunk * 8) = make_uint4(0u, 0u, 0u, 0u);
}

__device__ __forceinline__ void fma8(uint4 h, uint4 w, float* acc) {
    const __nv_bfloat162* hp = (const __nv_bfloat162*)&h;
    const __nv_bfloat162* wp = (const __nv_bfloat162*)&w;
    #pragma unroll
    for (int q = 0; q < 4; q++) {
        float2 hf = __bfloat1622float2(hp[q]);
        float2 wf = __bfloat1622float2(wp[q]);
        acc[2 * q]     = fmaf(hf.x, wf.x, acc[2 * q]);
        acc[2 * q + 1] = fmaf(hf.y, wf.y, acc[2 * q + 1]);
    }
}

__global__ __launch_bounds__(256) void k_dwc(const float* __restrict__ bias) {
    int tid = blockIdx.x * 256 + threadIdx.x;
    if (tid >= NPIX * 16) return;
    int c8 = (tid & 15) * 8;
    int pix = tid >> 4;
    int b = pix / HW, hw = pix % HW;
    int y = hw / WW, x = hw % WW;
    float acc[8];
    {
        float4 b0 = ldg4(bias + c8), b1 = ldg4(bias + c8 + 4);
        acc[0] = b0.x; acc[1] = b0.y; acc[2] = b0.z; acc[3] = b0.w;
        acc[4] = b1.x; acc[5] = b1.y; acc[6] = b1.z; acc[7] = b1.w;
    }
    #pragma unroll
    for (int ky = 0; ky < 3; ky++) {
        int yy = y + ky - 1;
        if (yy < 0 || yy >= HH) continue;
        #pragma unroll
        for (int kx = 0; kx < 3; kx++) {
            int xx = x + kx - 1;
            if (xx < 0 || xx >= WW) continue;
            uint4 hv = *(const uint4*)(g_h + ((size_t)b * HW + (size_t)yy * WW + xx) * DWC + c8);
            uint4 wv = *(const uint4*)(g_wbf + OFF_DWC + (ky * 3 + kx) * DWC + c8);
            fma8(hv, wv, acc);
        }
    }
    uint4 o;
    o.x = b2u(__floats2bfloat162_rn(acc[0], acc[1]));
    o.y = b2u(__floats2bfloat162_rn(acc[2], acc[3]));
    o.z = b2u(__floats2bfloat162_rn(acc[4], acc[5]));
    o.w = b2u(__floats2bfloat162_rn(acc[6], acc[7]));
    *(uint4*)(g_dw + (size_t)pix * DWC + c8) = o;
}

// ---------------- DCN sampler: warp per PIXEL, lane = (group, 4-ch chunk), uint2 gathers ----------------
__global__ __launch_bounds__(256) void k_sample() {
    __shared__ float som[8 * 112];
    int t = threadIdx.x;
    int base = blockIdx.x * 8;   // 8 pixels per block
    for (int i = t; i < 8 * 112; i += 256) som[i] = g_om[(size_t)base * 112 + i];
    __syncthreads();
    int wp = t >> 5, lane = t & 31;
    int pix = base + wp;
    int b = pix / HW, hw = pix % HW;
    int y = hw / WW, x = hw % WW;
    int g = lane >> 3, sub = lane & 7;
    const float* om = som + wp * 112 + g * 27;
    int gc = g * 32 + sub * 4;
    const __nv_bfloat16* vpb = g_vp + (size_t)b * HP * WP * DWC + gc;
    float acc0 = 0.f, acc1 = 0.f, acc2 = 0.f, acc3 = 0.f;
    #pragma unroll
    for (int k = 0; k < 9; k++) {
        float offx = om[k * 3 + 0];
        float offy = om[k * 3 + 1];
        float mask = om[k * 3 + 2];
        float px = (float)(x + (k % 3)) + offx;
        float py = (float)(y + (k / 3)) + offy;
        float x0f = floorf(px), y0f = floorf(py);
        float tx = px - x0f, ty = py - y0f;
        int x0 = (int)x0f, y0 = (int)y0f;
        #pragma unroll
        for (int dy = 0; dy < 2; dy++) {
            #pragma unroll
            for (int dx = 0; dx < 2; dx++) {
                int xi = x0 + dx, yi = y0 + dy;
                float wg = (dx ? tx : 1.f - tx) * (dy ? ty : 1.f - ty);
                bool valid = (xi >= 0) & (xi < WP) & (yi >= 0) & (yi < HP);
                wg = valid ? wg * mask : 0.f;
                int xc = min(max(xi, 0), WP - 1);
                int yc = min(max(yi, 0), HP - 1);
                uint2 hv = *(const uint2*)(vpb + ((size_t)yc * WP + xc) * DWC);
                __nv_bfloat162 p0, p1;
                memcpy(&p0, &hv.x, 4); memcpy(&p1, &hv.y, 4);
                float2 f0 = __bfloat1622float2(p0), f1 = __bfloat1622float2(p1);
                acc0 = fmaf(wg, f0.x, acc0);
                acc1 = fmaf(wg, f0.y, acc1);
                acc2 = fmaf(wg, f1.x, acc2);
                acc3 = fmaf(wg, f1.y, acc3);
            }
        }
    }
    uint2 o = make_uint2(b2u(__floats2bfloat162_rn(acc0, acc1)), b2u(__floats2bfloat162_rn(acc2, acc3)));
    *(uint2*)(g_s + (size_t)pix * DWC + gc) = o;
}

__global__ __launch_bounds__(256) void k_pool1() {
    __shared__ float red[256];
    int blk = blockIdx.x;
    int chunk = blk % 100;
    int bb = (blk / 100) & 1;
    int br = blk / 200;
    int pix0 = bb * HW + chunk * 256;
    int c = threadIdx.x & 63, sub = threadIdx.x >> 6;
    const float* f = g_feat + (size_t)br * NPIX * C0 + (size_t)(pix0 + sub * 64) * C0 + c;
    float s = 0.f;
    #pragma unroll 4
    for (int p = 0; p < 64; p++) s += f[(size_t)p * C0];
    red[threadIdx.x] = s;
    __syncthreads();
    if (sub == 0)
        g_part[blk * 64 + c] = red[c] + red[64 + c] + red[128 + c] + red[192 + c];
}

__global__ __launch_bounds__(256) void k_pool_scale(const float* __restrict__ sw,
                                                    const float* __restrict__ sb) {
    __shared__ float pooled[2 * 128];
    int t = threadIdx.x;
    int b = t >> 7, cc = t & 127;
    int br = cc >> 6, c = cc & 63;
    float s = 0.f;
    for (int ch = 0; ch < 100; ch++)
        s += g_part[((br * 2 + b) * 100 + ch) * 64 + c];
    pooled[b * 128 + cc] = s * (1.f / (float)HW);
    __syncthreads();
    float acc = sb[cc];
    #pragma unroll 4
    for (int k = 0; k < 128; k++) acc = fmaf(sw[cc * 128 + k], pooled[b * 128 + k], acc);
    g_scale[b * 128 + cc] = acc;
}

// ---------------- host launch ----------------
extern "C" void kernel_launch(void* const* d_in, const int* in_sizes, int n_in,
                              void* d_out, int out_size) {
    const float* x_l     = (const float*)d_in[0];
    const float* x_r     = (const float*)d_in[1];
    const float* ln1_g   = (const float*)d_in[2];
    const float* pw1_w   = (const float*)d_in[3];
    const float* pw1_b   = (const float*)d_in[4];
    const float* val_w   = (const float*)d_in[5];
    const float* val_b   = (const float*)d_in[6];
    const float* dwc_w   = (const float*)d_in[7];
    const float* dwc_b   = (const float*)d_in[8];
    const float* om_w    = (const float*)d_in[9];
    const float* om_b    = (const float*)d_in[10];
    const float* outp_w  = (const float*)d_in[11];
    const float* outp_b  = (const float*)d_in[12];
    const float* sca_w   = (const float*)d_in[13];
    const float* sca_b   = (const float*)d_in[14];
    const float* conv3_w = (const float*)d_in[15];
    const float* conv3_b = (const float*)d_in[16];
    const float* norm2_g = (const float*)d_in[17];
    const float* conv4_w = (const float*)d_in[18];
    const float* conv4_b = (const float*)d_in[19];
    const float* conv5_w = (const float*)d_in[20];
    const float* conv5_b = (const float*)d_in[21];
    const float* beta    = (const float*)d_in[22];
    const float* gamma   = (const float*)d_in[23];
    float* out = (float*)d_out;

    const int SM_PW1  = 64 * 132 * 4;                 // 33792
    const int SM_VAL  = 17408 + 17408;                // 34816
    const int SM_OM   = SM_VAL;
    const int SM_OUTP = 64 * 136 * 2 + 128 * 136 * 2; // 52224
    const int SM_C3   = 64 * 136 * 2 + 64 * 136 * 2;  // 34816
    const int SM_C4   = SM_OUTP;
    const int SM_C5   = 64 * 72 * 2 + 64 * 72 * 2;    // 18432

    cudaFuncSetAttribute(k_mm_pw1,   cudaFuncAttributeMaxDynamicSharedMemorySize, SM_PW1);
    cudaFuncSetAttribute(k_mm_val,   cudaFuncAttributeMaxDynamicSharedMemorySize, SM_VAL);
    cudaFuncSetAttribute(k_mm_om,    cudaFuncAttributeMaxDynamicSharedMemorySize, SM_OM);
    cudaFuncSetAttribute(k_mm_outp,  cudaFuncAttributeMaxDynamicSharedMemorySize, SM_OUTP);
    cudaFuncSetAttribute(k_mm_conv3, cudaFuncAttributeMaxDynamicSharedMemorySize, SM_C3);
    cudaFuncSetAttribute(k_mm_ln2c4, cudaFuncAttributeMaxDynamicSharedMemorySize, SM_C4);
    cudaFuncSetAttribute(k_mm_conv5, cudaFuncAttributeMaxDynamicSharedMemorySize, SM_C5);

    const int NBM = NPIX / 64;  // 800

    k_prep_w<<<dim3(64, 8), 256>>>(pw1_w, val_w, om_w, outp_w, conv3_w, conv4_w, conv5_w, dwc_w);
    k_zero_vp_border<<<(BB * 644 * 16 + 255) / 256, 256>>>();

    for (int br = 0; br < 2; br++) {
        const float* x = br ? x_r : x_l;
        k_mm_pw1<<<NBM, 128, SM_PW1>>>(x, ln1_g, pw1_b);
        k_mm_val<<<NBM, 128, SM_VAL>>>(val_b);
        k_dwc<<<NPIX * 16 / 256, 256>>>(dwc_b);
        k_mm_om<<<NBM, 128, SM_OM>>>(om_b);
        k_sample<<<NPIX / 8, 256>>>();
        k_mm_outp<<<NBM, 128, SM_OUTP>>>(outp_b, br);
    }

    k_pool1<<<400, 256>>>();
    k_pool_scale<<<1, 256>>>(sca_w, sca_b);
    k_mm_conv3<<<NBM, 128, SM_C3>>>(conv3_b, x_l, x_r, beta);
    k_mm_ln2c4<<<NBM, 128, SM_C4>>>(norm2_g, conv4_b);
    k_mm_conv5<<<NBM, 128, SM_C5>>>(conv5_b, gamma, out);
}